// round 10
// baseline (speedup 1.0000x reference)
#include <cuda_runtime.h>
#include <cuda_bf16.h>
#include <math.h>
#include <stdint.h>

// ---------------- problem constants ----------------
#define BATCH   8
#define CCH     256
#define LSEQ    4096
#define ROWS    (BATCH*LSEQ)   // 32768
#define DIN     1064
#define DINNER  512
#define CONVD   544
#define NH      8
#define HD      64
#define DS      16
#define EPS     1e-5f

#define SEG     64
#define SLEN    (LSEQ/SEG)
#define NBH     (BATCH*NH)
#define STATE   (HD*DS)

// ---------------- scratch ----------------
__device__ float2 g_stats[(size_t)ROWS];        // per-row (mu, rsigma)
__device__ float g_win[(size_t)CCH*DIN];        // TF32-rounded Win
__device__ float g_wouts[(size_t)DINNER*CCH];   // TF32-rounded Wout*rms_w
__device__ float g_zx [(size_t)ROWS*DIN];
__device__ float g_xbc[(size_t)ROWS*CONVD];     // only B/C cols [512,544) used
__device__ float g_dt [(size_t)ROWS*NH];
__device__ float g_da [(size_t)ROWS*NH];
__device__ float g_y  [(size_t)ROWS*DINNER];
__device__ float g_hend[(size_t)NBH*SEG*STATE];
__device__ float g_hin [(size_t)NBH*SEG*STATE];
__device__ float g_P   [(size_t)NBH*SEG];

// ---------------- helpers ----------------
__device__ __forceinline__ uint32_t f2tf32(float f) {
    uint32_t r;
    asm("cvt.rna.tf32.f32 %0, %1;" : "=r"(r) : "f"(f));
    return r;
}
__device__ __forceinline__ float fsig(float v) {
    return __fdividef(1.f, 1.f + __expf(-v));
}
__device__ __forceinline__ void cp16(float* s, const float* g) {
    uint32_t sa = (uint32_t)__cvta_generic_to_shared(s);
    asm volatile("cp.async.cg.shared.global [%0], [%1], 16;" :: "r"(sa), "l"(g));
}
__device__ __forceinline__ void cp8z(float* s, const float* g, bool p) {
    uint32_t sa = (uint32_t)__cvta_generic_to_shared(s);
    int sz = p ? 8 : 0;
    asm volatile("cp.async.ca.shared.global [%0], [%1], 8, %2;" :: "r"(sa), "l"(g), "r"(sz));
}
#define CP_COMMIT() asm volatile("cp.async.commit_group;")
#define CP_WAIT1()  asm volatile("cp.async.wait_group 1;")
#define CP_WAIT0()  asm volatile("cp.async.wait_group 0;")

#define MMA_TF32(acc, af, bf) \
    asm volatile( \
        "mma.sync.aligned.m16n8k8.row.col.f32.tf32.tf32.f32 " \
        "{%0,%1,%2,%3}, {%4,%5,%6,%7}, {%8,%9}, {%0,%1,%2,%3};" \
        : "+f"(acc[0]), "+f"(acc[1]), "+f"(acc[2]), "+f"(acc[3]) \
        : "r"(af[0]), "r"(af[1]), "r"(af[2]), "r"(af[3]), "r"(bf[0]), "r"(bf[1]))

// ---------------- kernel 0: precompute TF32 weights ----------------
__global__ void prep_kernel(const float* __restrict__ Win,
                            const float* __restrict__ Wout,
                            const float* __restrict__ rms_w)
{
    int i = blockIdx.x * 256 + threadIdx.x;
    if (i < CCH * DIN) g_win[i] = __uint_as_float(f2tf32(Win[i]));
    if (i < DINNER * CCH) {
        int k = i >> 8;
        g_wouts[i] = __uint_as_float(f2tf32(Wout[i] * rms_w[k]));
    }
}

// ---------------- kernel 1: LN stats only (mu, rsigma per row) ----------
__global__ __launch_bounds__(256) void stats_kernel(const float* __restrict__ x)
{
    __shared__ float s[256][33];
    __shared__ float s_mu[32], s_rs[32];
    const int b  = blockIdx.y;
    const int l0 = blockIdx.x * 32;
    const int t  = threadIdx.x;

#pragma unroll
    for (int i = 0; i < 32; i++) {
        int flat = i * 256 + t;
        int c  = flat >> 5;
        int lp = flat & 31;
        s[c][lp] = x[((size_t)b * CCH + c) * LSEQ + l0 + lp];
    }
    __syncthreads();

    const int wid = t >> 5, lane = t & 31;
    for (int j = wid; j < 32; j += 8) {
        float v = 0.f, v2 = 0.f;
#pragma unroll
        for (int k = 0; k < 8; k++) {
            float a = s[lane + 32 * k][j];
            v += a; v2 += a * a;
        }
#pragma unroll
        for (int o = 16; o; o >>= 1) {
            v  += __shfl_xor_sync(0xffffffffu, v,  o);
            v2 += __shfl_xor_sync(0xffffffffu, v2, o);
        }
        if (lane == 0) {
            float m = v * (1.f / 256.f);
            s_mu[j] = m;
            s_rs[j] = rsqrtf(v2 * (1.f / 256.f) - m * m + EPS);
        }
    }
    __syncthreads();
    if (t < 32)
        g_stats[(size_t)b * LSEQ + l0 + t] = make_float2(s_mu[t], s_rs[t]);
}

// ---------------- GEMM1 fused LN: zx = LN(x) @ win, TF32 ----------------
// A built on-the-fly from x (b,c,l) + per-row stats; k-major smem tile.
// dt/dA computed in epilogue (n-block 8 holds dt cols).
#define G1_STRIDE 136
#define G1_TSZ (32*G1_STRIDE)            // 4352 floats per buffer
#define SMEM_G1 (4*G1_TSZ*4 + 128*8)     // 70656 B

__global__ __launch_bounds__(256) void gemm1_kernel(
    const float* __restrict__ x, const float* __restrict__ gamma,
    const float* __restrict__ beta, const float* __restrict__ dt_bias,
    const float* __restrict__ A_log)
{
    extern __shared__ float dsm[];
    float* As = dsm;                       // [2][32][136]  k-major
    float* Bs = dsm + 2*G1_TSZ;            // [2][32][136]
    float2* sStats = (float2*)(dsm + 4*G1_TSZ);   // [128]

    const int t = threadIdx.x;
    const int warp = t >> 5, lane = t & 31;
    const int wm = warp & 3, wn = warp >> 2;
    const int m0 = blockIdx.y * 128;
    const int n0 = blockIdx.x * 128;
    const int g = lane >> 2, tg = lane & 3;
    const int N = DIN;
    const int b = m0 >> 12;
    const int l0 = m0 & (LSEQ - 1);
    const int cl = t >> 3;          // channel-local 0..31
    const int lseg = t & 7;         // 16-row chunk 0..7

    if (t < 128) sStats[t] = g_stats[(size_t)m0 + t];

    float acc[2][8][4];
#pragma unroll
    for (int mi = 0; mi < 2; mi++)
#pragma unroll
        for (int nj = 0; nj < 8; nj++)
#pragma unroll
            for (int q = 0; q < 4; q++) acc[mi][nj][q] = 0.f;

    auto issueB = [&](int tile, int buf) {
        const float* Bg = g_win + (size_t)(tile * 32) * N + n0;
        float* Bsb = Bs + buf * G1_TSZ;
#pragma unroll
        for (int i = 0; i < 8; i++) {
            int idx = t + i * 256;
            int kr = idx >> 6, nc = (idx & 63) << 1;
            cp8z(Bsb + kr * G1_STRIDE + nc, Bg + (size_t)kr * N + nc, n0 + nc < N);
        }
    };

    // prologue
    issueB(0, 0);
    CP_COMMIT();
    float4 xr[4];
    float gm, bt;
    {
        int c = cl;
        const float* xp = x + ((size_t)(b * CCH + c)) * LSEQ + l0 + lseg * 16;
#pragma unroll
        for (int j = 0; j < 4; j++) xr[j] = *(const float4*)(xp + j * 4);
        gm = __ldg(gamma + c);
        bt = __ldg(beta + c);
    }
    __syncthreads();   // sStats ready

    const int T = CCH / 32;   // 8
    for (int kt = 0; kt < T; kt++) {
        // A-fill: normalize + tf32 round + STS (k-major)
        {
            float* Asb = As + (kt & 1) * G1_TSZ;
#pragma unroll
            for (int j = 0; j < 4; j++) {
                int lb = lseg * 16 + j * 4;
                float2 s0 = sStats[lb + 0], s1 = sStats[lb + 1];
                float2 s2 = sStats[lb + 2], s3 = sStats[lb + 3];
                float4 o;
                o.x = __uint_as_float(f2tf32((xr[j].x - s0.x) * s0.y * gm + bt));
                o.y = __uint_as_float(f2tf32((xr[j].y - s1.x) * s1.y * gm + bt));
                o.z = __uint_as_float(f2tf32((xr[j].z - s2.x) * s2.y * gm + bt));
                o.w = __uint_as_float(f2tf32((xr[j].w - s3.x) * s3.y * gm + bt));
                *(float4*)(Asb + cl * G1_STRIDE + lb) = o;
            }
        }
        // prefetch next tile
        if (kt + 1 < T) {
            issueB(kt + 1, (kt + 1) & 1);
            CP_COMMIT();
            int c = (kt + 1) * 32 + cl;
            const float* xp = x + ((size_t)(b * CCH + c)) * LSEQ + l0 + lseg * 16;
#pragma unroll
            for (int j = 0; j < 4; j++) xr[j] = *(const float4*)(xp + j * 4);
            gm = __ldg(gamma + c);
            bt = __ldg(beta + c);
            CP_WAIT1();
        } else {
            CP_WAIT0();
        }
        __syncthreads();

        const float* Asb = As + (kt & 1) * G1_TSZ;
        const float* Bsb = Bs + (kt & 1) * G1_TSZ;
#pragma unroll
        for (int kk = 0; kk < 32; kk += 8) {
            uint32_t af[2][4];
#pragma unroll
            for (int mi = 0; mi < 2; mi++) {
                int mb = wm * 32 + mi * 16;
                af[mi][0] = __float_as_uint(Asb[(kk + tg    ) * G1_STRIDE + mb + g]);
                af[mi][1] = __float_as_uint(Asb[(kk + tg    ) * G1_STRIDE + mb + 8 + g]);
                af[mi][2] = __float_as_uint(Asb[(kk + 4 + tg) * G1_STRIDE + mb + g]);
                af[mi][3] = __float_as_uint(Asb[(kk + 4 + tg) * G1_STRIDE + mb + 8 + g]);
            }
            uint32_t bf[8][2];
#pragma unroll
            for (int nj = 0; nj < 8; nj++) {
                int nb = wn * 64 + nj * 8;
                bf[nj][0] = __float_as_uint(Bsb[(kk + tg    ) * G1_STRIDE + nb + g]);
                bf[nj][1] = __float_as_uint(Bsb[(kk + 4 + tg) * G1_STRIDE + nb + g]);
            }
#pragma unroll
            for (int mi = 0; mi < 2; mi++)
#pragma unroll
                for (int nj = 0; nj < 8; nj++) MMA_TF32(acc[mi][nj], af[mi], bf[nj]);
        }
        __syncthreads();
    }

    // epilogue: store zx
#pragma unroll
    for (int mi = 0; mi < 2; mi++) {
        int rbase = m0 + wm * 32 + mi * 16 + g;
#pragma unroll
        for (int nj = 0; nj < 8; nj++) {
            int col = n0 + wn * 64 + nj * 8 + 2 * tg;
            if (col < N) {
                *(float2*)(g_zx + (size_t)rbase * N + col) =
                    make_float2(acc[mi][nj][0], acc[mi][nj][1]);
                *(float2*)(g_zx + (size_t)(rbase + 8) * N + col) =
                    make_float2(acc[mi][nj][2], acc[mi][nj][3]);
            }
        }
    }
    // fused dt/dA: dt cols 1056..1063 live in n-block 8, wn==0, nj==4
    if (blockIdx.x == 8 && wn == 0) {
#pragma unroll
        for (int mi = 0; mi < 2; mi++) {
            int rb_ = m0 + wm * 32 + mi * 16 + g;
#pragma unroll
            for (int q = 0; q < 4; q++) {
                int h = 2 * tg + (q & 1);
                int row = rb_ + ((q >> 1) << 3);
                float v = acc[mi][4][q] + dt_bias[h];
                float d = (v > 20.f) ? v : log1pf(__expf(v));
                float Ah = -__expf(A_log[h]);
                g_dt[(size_t)row * NH + h] = d;
                g_da[(size_t)row * NH + h] = __expf(d * Ah);
            }
        }
    }
}

// ---------------- kernel 4: conv(4)+SiLU, B/C channels only ----------
#define TROW 8
#define NBC  32
__global__ void convbc_kernel(const float* __restrict__ cw,
                              const float* __restrict__ cb)
{
    int id = blockIdx.x * blockDim.x + threadIdx.x;
    if (id >= (ROWS / TROW) * NBC) return;
    int c  = DINNER + (id % NBC);     // 512..543
    int rb = id / NBC;
    int r0 = rb * TROW;
    int l0 = r0 & (LSEQ - 1);

    const float* col = g_zx + DINNER + c;
    float w0 = cw[c * 4 + 0], w1 = cw[c * 4 + 1];
    float w2 = cw[c * 4 + 2], w3 = cw[c * 4 + 3];
    float bias = cb[c];

    float vm3 = 0.f, vm2 = 0.f, vm1 = 0.f;
    if (l0 != 0) {
        vm3 = col[(size_t)(r0 - 3) * DIN];
        vm2 = col[(size_t)(r0 - 2) * DIN];
        vm1 = col[(size_t)(r0 - 1) * DIN];
    }
#pragma unroll
    for (int i = 0; i < TROW; i++) {
        float v = col[(size_t)(r0 + i) * DIN];
        float acc = bias + w3 * v + w2 * vm1 + w1 * vm2 + w0 * vm3;
        g_xbc[(size_t)(r0 + i) * CONVD + c] = acc * fsig(acc);
        vm3 = vm2; vm2 = vm1; vm1 = v;
    }
}

// ---------------- kernel 5a: segment-local scan, fused x-conv, pipelined ---
__global__ __launch_bounds__(64) void scanA_kernel(
    const float* __restrict__ Dp, const float* __restrict__ cw,
    const float* __restrict__ cb)
{
    const int blk = blockIdx.x;
    const int bh  = blk / SEG;
    const int seg = blk % SEG;
    const int b = bh >> 3, h = bh & 7;
    const int p = threadIdx.x;
    const float Dh = Dp[h];

    const int c = h * HD + p;
    const float w0 = cw[c * 4 + 0], w1 = cw[c * 4 + 1];
    const float w2 = cw[c * 4 + 2], w3 = cw[c * 4 + 3];
    const float cbias = cb[c];
    const float* colz = g_zx + DINNER + c;

    float hs[DS];
#pragma unroll
    for (int n = 0; n < DS; n++) hs[n] = 0.f;
    float prod = 1.f;

    const size_t r0 = (size_t)b * LSEQ + seg * SLEN;
    float vm3 = 0.f, vm2 = 0.f, vm1 = 0.f;
    if (seg != 0) {
        vm3 = colz[(r0 - 3) * DIN];
        vm2 = colz[(r0 - 2) * DIN];
        vm1 = colz[(r0 - 1) * DIN];
    }

    float dav = g_da[r0 * NH + h];
    float dtv = g_dt[r0 * NH + h];
    float vz  = colz[r0 * DIN];
    const float* bp = g_xbc + r0 * CONVD + DINNER;
    float4 B0 = *(const float4*)(bp +  0), B1 = *(const float4*)(bp +  4);
    float4 B2 = *(const float4*)(bp +  8), B3 = *(const float4*)(bp + 12);
    float4 C0 = *(const float4*)(bp + 16), C1 = *(const float4*)(bp + 20);
    float4 C2 = *(const float4*)(bp + 24), C3 = *(const float4*)(bp + 28);

    for (int l = 0; l < SLEN; l++) {
        const size_t r = r0 + l;
        float dav_n = dav, dtv_n = dtv, vz_n = vz;
        float4 nB0 = B0, nB1 = B1, nB2 = B2, nB3 = B3;
        float4 nC0 = C0, nC1 = C1, nC2 = C2, nC3 = C3;
        if (l + 1 < SLEN) {
            const size_t rn = r + 1;
            dav_n = g_da[rn * NH + h];
            dtv_n = g_dt[rn * NH + h];
            vz_n  = colz[rn * DIN];
            const float* bpn = g_xbc + rn * CONVD + DINNER;
            nB0 = *(const float4*)(bpn +  0); nB1 = *(const float4*)(bpn +  4);
            nB2 = *(const float4*)(bpn +  8); nB3 = *(const float4*)(bpn + 12);
            nC0 = *(const float4*)(bpn + 16); nC1 = *(const float4*)(bpn + 20);
            nC2 = *(const float4*)(bpn + 24); nC3 = *(const float4*)(bpn + 28);
        }

        prod *= dav;
        float ca = cbias + w3 * vz + w2 * vm1 + w1 * vm2 + w0 * vm3;
        float xv = ca * fsig(ca);
        vm3 = vm2; vm2 = vm1; vm1 = vz;

        float bb[DS] = {B0.x,B0.y,B0.z,B0.w, B1.x,B1.y,B1.z,B1.w,
                        B2.x,B2.y,B2.z,B2.w, B3.x,B3.y,B3.z,B3.w};
        float cc[DS] = {C0.x,C0.y,C0.z,C0.w, C1.x,C1.y,C1.z,C1.w,
                        C2.x,C2.y,C2.z,C2.w, C3.x,C3.y,C3.z,C3.w};

        float t1 = dtv * xv;
        float yv0 = 0.f, yv1 = 0.f;
#pragma unroll
        for (int n = 0; n < DS; n += 2) {
            hs[n]   = fmaf(dav, hs[n],   t1 * bb[n]);
            hs[n+1] = fmaf(dav, hs[n+1], t1 * bb[n+1]);
            yv0 = fmaf(hs[n],   cc[n],   yv0);
            yv1 = fmaf(hs[n+1], cc[n+1], yv1);
        }
        g_y[r * DINNER + h * HD + p] = yv0 + yv1 + Dh * xv;

        dav = dav_n; dtv = dtv_n; vz = vz_n;
        B0 = nB0; B1 = nB1; B2 = nB2; B3 = nB3;
        C0 = nC0; C1 = nC1; C2 = nC2; C3 = nC3;
    }

    float* he = g_hend + ((size_t)bh * SEG + seg) * STATE + p * DS;
#pragma unroll
    for (int n = 0; n < DS; n += 4)
        *(float4*)(he + n) = make_float4(hs[n], hs[n+1], hs[n+2], hs[n+3]);
    if (p == 0) g_P[(size_t)bh * SEG + seg] = prod;
}

// ---------------- kernel 5b: compose segment states ----------------
__global__ __launch_bounds__(1024) void scanB_kernel()
{
    const int bh = blockIdx.x;
    const int pn = threadIdx.x;
    __shared__ float sP[SEG];
    if (pn < SEG) sP[pn] = g_P[(size_t)bh * SEG + pn];
    __syncthreads();

    float h = 0.f;
    const size_t base = (size_t)bh * SEG * STATE + pn;
    for (int seg = 0; seg < SEG; seg++) {
        g_hin[base + (size_t)seg * STATE] = h;
        h = fmaf(sP[seg], h, g_hend[base + (size_t)seg * STATE]);
    }
}

// ---------------- kernel 5c: cross-segment correction, pipelined ---------
__global__ __launch_bounds__(64) void scanC_kernel()
{
    const int blk = blockIdx.x;
    const int bh  = blk / (SEG - 1);
    const int seg = blk % (SEG - 1) + 1;
    const int b = bh >> 3, h = bh & 7;
    const int p = threadIdx.x;

    float hi[DS];
    const float* hp = g_hin + ((size_t)bh * SEG + seg) * STATE + p * DS;
#pragma unroll
    for (int n = 0; n < DS; n += 4) {
        float4 v = *(const float4*)(hp + n);
        hi[n] = v.x; hi[n+1] = v.y; hi[n+2] = v.z; hi[n+3] = v.w;
    }

    float cp = 1.f;
    const size_t r0 = (size_t)b * LSEQ + seg * SLEN;

    float dav = g_da[r0 * NH + h];
    const float* bp0 = g_xbc + r0 * CONVD + DINNER;
    float4 C0 = *(const float4*)(bp0 + 16), C1 = *(const float4*)(bp0 + 20);
    float4 C2 = *(const float4*)(bp0 + 24), C3 = *(const float4*)(bp0 + 28);

    for (int l = 0; l < SLEN; l++) {
        const size_t r = r0 + l;
        float dav_n = dav;
        float4 nC0 = C0, nC1 = C1, nC2 = C2, nC3 = C3;
        if (l + 1 < SLEN) {
            const size_t rn = r + 1;
            dav_n = g_da[rn * NH + h];
            const float* bpn = g_xbc + rn * CONVD + DINNER;
            nC0 = *(const float4*)(bpn + 16); nC1 = *(const float4*)(bpn + 20);
            nC2 = *(const float4*)(bpn + 24); nC3 = *(const float4*)(bpn + 28);
        }

        cp *= dav;
        float cc[DS] = {C0.x,C0.y,C0.z,C0.w, C1.x,C1.y,C1.z,C1.w,
                        C2.x,C2.y,C2.z,C2.w, C3.x,C3.y,C3.z,C3.w};
        float d0 = 0.f, d1 = 0.f;
#pragma unroll
        for (int n = 0; n < DS; n += 2) {
            d0 = fmaf(hi[n],   cc[n],   d0);
            d1 = fmaf(hi[n+1], cc[n+1], d1);
        }
        g_y[r * DINNER + h * HD + p] += cp * (d0 + d1);

        dav = dav_n;
        C0 = nC0; C1 = nC1; C2 = nC2; C3 = nC3;
    }
}

// ---------------- GEMM2 fused, pipelined (R7 version): gate + RMSNorm +
// out_proj + transpose + residual.
#define G2_ASTRIDE 36
#define G2_BSTRIDE 264
#define G2_BSZ (32*G2_BSTRIDE)
#define G2_POOLF (64*G2_ASTRIDE + 2*G2_BSZ)    // 19200 floats
#define SMEM_G2 (G2_POOLF*4)                   // 76800 bytes

__global__ __launch_bounds__(256) void gemm2_fused_kernel(
    const float* __restrict__ x, float* __restrict__ out)
{
    extern __shared__ float pool[];
    float* As = pool;                   // [64][36]
    float* Bs = pool + 64 * G2_ASTRIDE; // [2][32][264]
    const int t = threadIdx.x;
    const int warp = t >> 5, lane = t & 31;
    const int wm = warp & 1, wn = warp >> 1;
    const int m0 = blockIdx.x * 64;
    const int g = lane >> 2, tg = lane & 3;
    const int r0 = t >> 3, kc0 = (t & 7) << 2;

    float acc[2][8][4];
#pragma unroll
    for (int mi = 0; mi < 2; mi++)
#pragma unroll
        for (int nj = 0; nj < 8; nj++)
#pragma unroll
            for (int q = 0; q < 4; q++) acc[mi][nj][q] = 0.f;
    float sq0 = 0.f, sq1 = 0.f;

    auto issueB = [&](int k0, int buf) {
        float* Bsb = Bs + buf * G2_BSZ;
        const float* Wg = g_wouts + (size_t)k0 * CCH;
#pragma unroll
        for (int i = 0; i < 8; i++) {
            int idx = t + i * 256;
            int kr = idx >> 6, nc = (idx & 63) << 2;
            cp16(Bsb + kr * G2_BSTRIDE + nc, Wg + (size_t)kr * CCH + nc);
        }
    };

    issueB(0, 0);
    CP_COMMIT();
    float4 ry0, ry1, rz0, rz1;
    {
        size_t rra = (size_t)(m0 + r0);
        size_t rrb = (size_t)(m0 + r0 + 32);
        ry0 = *(const float4*)(g_y  + rra * DINNER + kc0);
        rz0 = *(const float4*)(g_zx + rra * DIN    + kc0);
        ry1 = *(const float4*)(g_y  + rrb * DINNER + kc0);
        rz1 = *(const float4*)(g_zx + rrb * DIN    + kc0);
    }

    const int NT = DINNER / 32;   // 16
    for (int kt = 0; kt < NT; kt++) {
        {
            float v0 = ry0.x * (rz0.x * fsig(rz0.x));
            float v1 = ry0.y * (rz0.y * fsig(rz0.y));
            float v2 = ry0.z * (rz0.z * fsig(rz0.z));
            float v3 = ry0.w * (rz0.w * fsig(rz0.w));
            As[r0 * G2_ASTRIDE + kc0 + 0] = __uint_as_float(f2tf32(v0));
            As[r0 * G2_ASTRIDE + kc0 + 1] = __uint_as_float(f2tf32(v1));
            As[r0 * G2_ASTRIDE + kc0 + 2] = __uint_as_float(f2tf32(v2));
            As[r0 * G2_ASTRIDE + kc0 + 3] = __uint_as_float(f2tf32(v3));
            sq0 += v0*v0 + v1*v1 + v2*v2 + v3*v3;
            float u0 = ry1.x * (rz1.x * fsig(rz1.x));
            float u1 = ry1.y * (rz1.y * fsig(rz1.y));
            float u2 = ry1.z * (rz1.z * fsig(rz1.z));
            float u3 = ry1.w * (rz1.w * fsig(rz1.w));
            As[(r0 + 32) * G2_ASTRIDE + kc0 + 0] = __uint_as_float(f2tf32(u0));
            As[(r0 + 32) * G2_ASTRIDE + kc0 + 1] = __uint_as_float(f2tf32(u1));
            As[(r0 + 32) * G2_ASTRIDE + kc0 + 2] = __uint_as_float(f2tf32(u2));
            As[(r0 + 32) * G2_ASTRIDE + kc0 + 3] = __uint_as_float(f2tf32(u3));
            sq1 += u0*u0 + u1*u1 + u2*u2 + u3*u3;
        }
        if (kt + 1 < NT) {
            issueB((kt + 1) * 32, (kt + 1) & 1);
            CP_COMMIT();
            int k1 = (kt + 1) * 32 + kc0;
            size_t rra = (size_t)(m0 + r0);
            size_t rrb = (size_t)(m0 + r0 + 32);
            ry0 = *(const float4*)(g_y  + rra * DINNER + k1);
            rz0 = *(const float4*)(g_zx + rra * DIN    + k1);
            ry1 = *(const float4*)(g_y  + rrb * DINNER + k1);
            rz1 = *(const float4*)(g_zx + rrb * DIN    + k1);
            CP_WAIT1();
        } else {
            CP_WAIT0();
        }
        __syncthreads();

        const float* Bsb = Bs + (kt & 1) * G2_BSZ;
#pragma unroll
        for (int kk = 0; kk < 32; kk += 8) {
            uint32_t af[2][4];
#pragma unroll
            for (int mi = 0; mi < 2; mi++) {
                int mb = wm * 32 + mi * 16;
                af[mi][0] = __float_as_uint(As[(mb + g    ) * G2_ASTRIDE + kk + tg]);
                af[mi][1] = __float_as_uint(As[(mb + 8 + g) * G2_ASTRIDE + kk + tg]);
                af[mi][2] = __float_as_uint(As[(mb + g    ) * G2_ASTRIDE + kk + 4 + tg]);
                af[mi][3] = __float_as_uint(As[(mb + 8 + g) * G2_ASTRIDE + kk + 4 + tg]);
            }
            uint32_t bf[8][2];
#pragma unroll
            for (int nj = 0; nj < 8; nj++) {
                int nb = wn * 64 + nj * 8;
                bf[nj][0] = __float_as_uint(Bsb[(kk + tg    ) * G2_BSTRIDE + nb + g]);
                bf[nj][1] = __float_as_uint(Bsb[(kk + 4 + tg) * G2_BSTRIDE + nb + g]);
            }
#pragma unroll
            for (int mi = 0; mi < 2; mi++)
#pragma unroll
                for (int nj = 0; nj < 8; nj++) MMA_TF32(acc[mi][nj], af[mi], bf[nj]);
        }
        __syncthreads();
    }

    // rn reduction
    float* sq = pool;
    sq[r0 * 8 + (t & 7)] = sq0;
    sq[(r0 + 32) * 8 + (t & 7)] = sq1;
    __syncthreads();
    float* rn = pool + 512;
    if (t < 64) {
        float s = 0.f;
#pragma unroll
        for (int j = 0; j < 8; j++) s += sq[t * 8 + j];
        rn[t] = rsqrtf(s * (1.f / (float)DINNER) + EPS);
    }
    __syncthreads();
    float rsc[2][2];
#pragma unroll
    for (int mi = 0; mi < 2; mi++) {
        rsc[mi][0] = rn[wm * 32 + mi * 16 + g];
        rsc[mi][1] = rn[wm * 32 + mi * 16 + 8 + g];
    }
    __syncthreads();

    // epilogue: transpose + residual
    float* epi = pool;
    const int b  = m0 >> 12;
    const int l0 = m0 & (LSEQ - 1);
#pragma unroll
    for (int cj = 0; cj < 4; cj++) {
        if (wn == cj) {
#pragma unroll
            for (int mi = 0; mi < 2; mi++)
#pragma unroll
                for (int nj = 0; nj < 8; nj++)
#pragma unroll
                    for (int q = 0; q < 4; q++) {
                        int Rl = wm * 32 + mi * 16 + g + ((q >> 1) << 3);
                        int cl = nj * 8 + 2 * tg + (q & 1);
                        epi[cl * 68 + Rl] = acc[mi][nj][q] * rsc[mi][q >> 1];
                    }
        }
        __syncthreads();
        {
            int c = t >> 2, sg2 = t & 3;
            size_t ob = ((size_t)b * CCH + cj * 64 + c) * LSEQ + l0 + sg2 * 16;
#pragma unroll
            for (int j = 0; j < 4; j++) {
                float4 e  = *(float4*)(epi + c * 68 + sg2 * 16 + j * 4);
                float4 xr = *(const float4*)(x + ob + j * 4);
                e.x += xr.x; e.y += xr.y; e.z += xr.z; e.w += xr.w;
                *(float4*)(out + ob + j * 4) = e;
            }
        }
        __syncthreads();
    }
}

extern "C" void kernel_launch(void* const* d_in, const int* in_sizes, int n_in,
                              void* d_out, int out_size)
{
    const float* x       = (const float*)d_in[0];
    const float* ln_g    = (const float*)d_in[1];
    const float* ln_b    = (const float*)d_in[2];
    const float* Win     = (const float*)d_in[3];
    const float* Wout    = (const float*)d_in[4];
    const float* conv_w  = (const float*)d_in[5];
    const float* conv_b  = (const float*)d_in[6];
    const float* dt_bias = (const float*)d_in[7];
    const float* A_log   = (const float*)d_in[8];
    const float* Dp      = (const float*)d_in[9];
    const float* rms_w   = (const float*)d_in[10];
    float* out = (float*)d_out;

    cudaFuncSetAttribute(gemm1_kernel,
                         cudaFuncAttributeMaxDynamicSharedMemorySize, SMEM_G1);
    cudaFuncSetAttribute(gemm2_fused_kernel,
                         cudaFuncAttributeMaxDynamicSharedMemorySize, SMEM_G2);

    // 0) precompute TF32 weights
    prep_kernel<<<(CCH * DIN + 255) / 256, 256>>>(Win, Wout, rms_w);

    // 1) LN stats
    stats_kernel<<<dim3(LSEQ / 32, BATCH), 256>>>(x);

    // 2) in_proj GEMM with fused LN + dt/dA epilogue
    gemm1_kernel<<<dim3((DIN + 127) / 128, ROWS / 128), 256, SMEM_G1>>>(
        x, ln_g, ln_b, dt_bias, A_log);

    // 3) conv + silu, B/C channels only
    convbc_kernel<<<((ROWS / TROW) * NBC + 255) / 256, 256>>>(conv_w, conv_b);

    // 4) segmented SSM scan (x-conv fused into scanA)
    scanA_kernel<<<NBH * SEG, HD>>>(Dp, conv_w, conv_b);
    scanB_kernel<<<NBH, STATE>>>();
    scanC_kernel<<<NBH * (SEG - 1), HD>>>();

    // 5) fused pipelined: gate + rmsnorm + out_proj + transpose + residual (R7)
    gemm2_fused_kernel<<<ROWS / 64, 256, SMEM_G2>>>(x, out);
}

// round 12
// speedup vs baseline: 1.3207x; 1.3207x over previous
#include <cuda_runtime.h>
#include <cuda_bf16.h>
#include <math.h>
#include <stdint.h>

// ---------------- problem constants ----------------
#define BATCH   8
#define CCH     256
#define LSEQ    4096
#define ROWS    (BATCH*LSEQ)   // 32768
#define DIN     1064
#define DINNER  512
#define CONVD   544
#define NH      8
#define HD      64
#define DS      16
#define EPS     1e-5f

#define SEG     64
#define SLEN    (LSEQ/SEG)
#define NBH     (BATCH*NH)
#define STATE   (HD*DS)

// ---------------- scratch ----------------
__device__ float2 g_stats[(size_t)ROWS];        // per-row (mu, rsigma)
__device__ float g_win[(size_t)CCH*DIN];        // TF32-rounded Win
__device__ float g_wouts[(size_t)DINNER*CCH];   // TF32-rounded Wout*rms_w
__device__ float g_zx [(size_t)ROWS*DIN];
__device__ float g_xbc[(size_t)ROWS*CONVD];     // only B/C cols [512,544) used
__device__ float g_dt [(size_t)ROWS*NH];
__device__ float g_da [(size_t)ROWS*NH];
__device__ float g_y  [(size_t)ROWS*DINNER];
__device__ float g_hend[(size_t)NBH*SEG*STATE];
__device__ float g_hin [(size_t)NBH*SEG*STATE];
__device__ float g_P   [(size_t)NBH*SEG];

// ---------------- helpers ----------------
__device__ __forceinline__ uint32_t f2tf32(float f) {
    uint32_t r;
    asm("cvt.rna.tf32.f32 %0, %1;" : "=r"(r) : "f"(f));
    return r;
}
__device__ __forceinline__ float fsig(float v) {
    return __fdividef(1.f, 1.f + __expf(-v));
}
__device__ __forceinline__ void cp16(float* s, const float* g) {
    uint32_t sa = (uint32_t)__cvta_generic_to_shared(s);
    asm volatile("cp.async.cg.shared.global [%0], [%1], 16;" :: "r"(sa), "l"(g));
}
__device__ __forceinline__ void cp8z(float* s, const float* g, bool p) {
    uint32_t sa = (uint32_t)__cvta_generic_to_shared(s);
    int sz = p ? 8 : 0;
    asm volatile("cp.async.ca.shared.global [%0], [%1], 8, %2;" :: "r"(sa), "l"(g), "r"(sz));
}
#define CP_COMMIT() asm volatile("cp.async.commit_group;")
#define CP_WAIT1()  asm volatile("cp.async.wait_group 1;")
#define CP_WAIT0()  asm volatile("cp.async.wait_group 0;")

#define MMA_TF32(acc, af, bf) \
    asm volatile( \
        "mma.sync.aligned.m16n8k8.row.col.f32.tf32.tf32.f32 " \
        "{%0,%1,%2,%3}, {%4,%5,%6,%7}, {%8,%9}, {%0,%1,%2,%3};" \
        : "+f"(acc[0]), "+f"(acc[1]), "+f"(acc[2]), "+f"(acc[3]) \
        : "r"(af[0]), "r"(af[1]), "r"(af[2]), "r"(af[3]), "r"(bf[0]), "r"(bf[1]))

// ---------------- kernel 0: precompute TF32 weights ----------------
__global__ void prep_kernel(const float* __restrict__ Win,
                            const float* __restrict__ Wout,
                            const float* __restrict__ rms_w)
{
    int i = blockIdx.x * 256 + threadIdx.x;
    if (i < CCH * DIN) g_win[i] = __uint_as_float(f2tf32(Win[i]));
    if (i < DINNER * CCH) {
        int k = i >> 8;
        g_wouts[i] = __uint_as_float(f2tf32(Wout[i] * rms_w[k]));
    }
}

// ---------------- kernel 1: LN stats only (mu, rsigma per row) ----------
__global__ __launch_bounds__(256) void stats_kernel(const float* __restrict__ x)
{
    __shared__ float s[256][33];
    __shared__ float s_mu[32], s_rs[32];
    const int b  = blockIdx.y;
    const int l0 = blockIdx.x * 32;
    const int t  = threadIdx.x;

#pragma unroll
    for (int i = 0; i < 32; i++) {
        int flat = i * 256 + t;
        int c  = flat >> 5;
        int lp = flat & 31;
        s[c][lp] = x[((size_t)b * CCH + c) * LSEQ + l0 + lp];
    }
    __syncthreads();

    const int wid = t >> 5, lane = t & 31;
    for (int j = wid; j < 32; j += 8) {
        float v = 0.f, v2 = 0.f;
#pragma unroll
        for (int k = 0; k < 8; k++) {
            float a = s[lane + 32 * k][j];
            v += a; v2 += a * a;
        }
#pragma unroll
        for (int o = 16; o; o >>= 1) {
            v  += __shfl_xor_sync(0xffffffffu, v,  o);
            v2 += __shfl_xor_sync(0xffffffffu, v2, o);
        }
        if (lane == 0) {
            float m = v * (1.f / 256.f);
            s_mu[j] = m;
            s_rs[j] = rsqrtf(v2 * (1.f / 256.f) - m * m + EPS);
        }
    }
    __syncthreads();
    if (t < 32)
        g_stats[(size_t)b * LSEQ + l0 + t] = make_float2(s_mu[t], s_rs[t]);
}

// ---------------- GEMM1: zx = LN(x) @ win, TF32, cp.async 2-stage --------
// A = raw x strips via cp.async (k-major); normalization applied at
// fragment-read time (per-thread mu/rs regs + smem gamma/beta).
// dt/dA fused in epilogue.
#define G1_STRIDE 136
#define G1_TSZ (32*G1_STRIDE)                 // 4352 floats per buffer
#define SMEM_G1 (4*G1_TSZ*4 + 1024 + 2048)    // 72704 B

__global__ __launch_bounds__(256) void gemm1_kernel(
    const float* __restrict__ x, const float* __restrict__ gamma,
    const float* __restrict__ beta, const float* __restrict__ dt_bias,
    const float* __restrict__ A_log)
{
    extern __shared__ float dsm[];
    float* Xs = dsm;                              // [2][32][136] raw x, k-major
    float* Bs = dsm + 2*G1_TSZ;                   // [2][32][136]
    float2* sStats = (float2*)(dsm + 4*G1_TSZ);   // [128]
    float* sGamma = dsm + 4*G1_TSZ + 256;         // [256]
    float* sBeta  = sGamma + 256;                 // [256]

    const int t = threadIdx.x;
    const int warp = t >> 5, lane = t & 31;
    const int wm = warp & 3, wn = warp >> 2;
    const int m0 = blockIdx.y * 128;
    const int n0 = blockIdx.x * 128;
    const int g = lane >> 2, tg = lane & 3;
    const int N = DIN;
    const int b = m0 >> 12;
    const int l0 = m0 & (LSEQ - 1);

    if (t < 128) sStats[t] = g_stats[(size_t)m0 + t];
    sGamma[t] = gamma[t];
    sBeta[t]  = beta[t];

    float acc[2][8][4];
#pragma unroll
    for (int mi = 0; mi < 2; mi++)
#pragma unroll
        for (int nj = 0; nj < 8; nj++)
#pragma unroll
            for (int q = 0; q < 4; q++) acc[mi][nj][q] = 0.f;

    auto issueA = [&](int tile, int buf) {
        const float* base = x + ((size_t)(b * CCH + tile * 32)) * LSEQ + l0;
        float* Xb = Xs + buf * G1_TSZ;
#pragma unroll
        for (int i = 0; i < 4; i++) {
            int idx = t + i * 256;
            int c = idx >> 5, lw = idx & 31;
            cp16(Xb + c * G1_STRIDE + lw * 4, base + (size_t)c * LSEQ + lw * 4);
        }
    };
    auto issueB = [&](int tile, int buf) {
        const float* Bg = g_win + (size_t)(tile * 32) * N + n0;
        float* Bsb = Bs + buf * G1_TSZ;
#pragma unroll
        for (int i = 0; i < 8; i++) {
            int idx = t + i * 256;
            int kr = idx >> 6, nc = (idx & 63) << 1;
            cp8z(Bsb + kr * G1_STRIDE + nc, Bg + (size_t)kr * N + nc, n0 + nc < N);
        }
    };

    issueA(0, 0);
    issueB(0, 0);
    CP_COMMIT();
    __syncthreads();   // sStats / sGamma ready

    // per-thread LN constants for this thread's 4 l-positions
    float mu_[4], rs_[4];
#pragma unroll
    for (int j = 0; j < 4; j++) {
        float2 s = sStats[wm * 32 + j * 8 + g];
        mu_[j] = s.x; rs_[j] = s.y;
    }

    const int T = CCH / 32;   // 8
    for (int kt = 0; kt < T; kt++) {
        if (kt + 1 < T) {
            issueA(kt + 1, (kt + 1) & 1);
            issueB(kt + 1, (kt + 1) & 1);
            CP_COMMIT();
            CP_WAIT1();
        } else {
            CP_WAIT0();
        }
        __syncthreads();

        const float* Xb = Xs + (kt & 1) * G1_TSZ;
        const float* Bb = Bs + (kt & 1) * G1_TSZ;
#pragma unroll
        for (int kk = 0; kk < 32; kk += 8) {
            int c0 = kt * 32 + kk + tg, c1 = c0 + 4;
            float ga0 = sGamma[c0], be0 = sBeta[c0];
            float ga1 = sGamma[c1], be1 = sBeta[c1];
            uint32_t af[2][4];
#pragma unroll
            for (int mi = 0; mi < 2; mi++) {
                int mb = wm * 32 + mi * 16;
                float sA = rs_[2*mi]   * ga0, hA = be0 - mu_[2*mi]   * sA;
                float sB = rs_[2*mi+1] * ga0, hB = be0 - mu_[2*mi+1] * sB;
                float sC = rs_[2*mi]   * ga1, hC = be1 - mu_[2*mi]   * sC;
                float sD = rs_[2*mi+1] * ga1, hD = be1 - mu_[2*mi+1] * sD;
                af[mi][0] = f2tf32(fmaf(Xb[(kk + tg    ) * G1_STRIDE + mb + g    ], sA, hA));
                af[mi][1] = f2tf32(fmaf(Xb[(kk + tg    ) * G1_STRIDE + mb + 8 + g], sB, hB));
                af[mi][2] = f2tf32(fmaf(Xb[(kk + 4 + tg) * G1_STRIDE + mb + g    ], sC, hC));
                af[mi][3] = f2tf32(fmaf(Xb[(kk + 4 + tg) * G1_STRIDE + mb + 8 + g], sD, hD));
            }
            uint32_t bf[8][2];
#pragma unroll
            for (int nj = 0; nj < 8; nj++) {
                int nb = wn * 64 + nj * 8;
                bf[nj][0] = __float_as_uint(Bb[(kk + tg    ) * G1_STRIDE + nb + g]);
                bf[nj][1] = __float_as_uint(Bb[(kk + 4 + tg) * G1_STRIDE + nb + g]);
            }
#pragma unroll
            for (int mi = 0; mi < 2; mi++)
#pragma unroll
                for (int nj = 0; nj < 8; nj++) MMA_TF32(acc[mi][nj], af[mi], bf[nj]);
        }
        __syncthreads();
    }

    // epilogue: store zx
#pragma unroll
    for (int mi = 0; mi < 2; mi++) {
        int rbase = m0 + wm * 32 + mi * 16 + g;
#pragma unroll
        for (int nj = 0; nj < 8; nj++) {
            int col = n0 + wn * 64 + nj * 8 + 2 * tg;
            if (col < N) {
                *(float2*)(g_zx + (size_t)rbase * N + col) =
                    make_float2(acc[mi][nj][0], acc[mi][nj][1]);
                *(float2*)(g_zx + (size_t)(rbase + 8) * N + col) =
                    make_float2(acc[mi][nj][2], acc[mi][nj][3]);
            }
        }
    }
    // fused dt/dA: dt cols 1056..1063 live in n-block 8, wn==0, nj==4
    if (blockIdx.x == 8 && wn == 0) {
#pragma unroll
        for (int mi = 0; mi < 2; mi++) {
            int rb_ = m0 + wm * 32 + mi * 16 + g;
#pragma unroll
            for (int q = 0; q < 4; q++) {
                int h = 2 * tg + (q & 1);
                int row = rb_ + ((q >> 1) << 3);
                float v = acc[mi][4][q] + dt_bias[h];
                float d = (v > 20.f) ? v : log1pf(__expf(v));
                float Ah = -__expf(A_log[h]);
                g_dt[(size_t)row * NH + h] = d;
                g_da[(size_t)row * NH + h] = __expf(d * Ah);
            }
        }
    }
}

// ---------------- kernel 4: conv(4)+SiLU, B/C channels only ----------
#define TROW 8
#define NBC  32
__global__ void convbc_kernel(const float* __restrict__ cw,
                              const float* __restrict__ cb)
{
    int id = blockIdx.x * blockDim.x + threadIdx.x;
    if (id >= (ROWS / TROW) * NBC) return;
    int c  = DINNER + (id % NBC);     // 512..543
    int rb = id / NBC;
    int r0 = rb * TROW;
    int l0 = r0 & (LSEQ - 1);

    const float* col = g_zx + DINNER + c;
    float w0 = cw[c * 4 + 0], w1 = cw[c * 4 + 1];
    float w2 = cw[c * 4 + 2], w3 = cw[c * 4 + 3];
    float bias = cb[c];

    float vm3 = 0.f, vm2 = 0.f, vm1 = 0.f;
    if (l0 != 0) {
        vm3 = col[(size_t)(r0 - 3) * DIN];
        vm2 = col[(size_t)(r0 - 2) * DIN];
        vm1 = col[(size_t)(r0 - 1) * DIN];
    }
#pragma unroll
    for (int i = 0; i < TROW; i++) {
        float v = col[(size_t)(r0 + i) * DIN];
        float acc = bias + w3 * v + w2 * vm1 + w1 * vm2 + w0 * vm3;
        g_xbc[(size_t)(r0 + i) * CONVD + c] = acc * fsig(acc);
        vm3 = vm2; vm2 = vm1; vm1 = v;
    }
}

// ---------------- kernel 5a: segment-local scan, fused x-conv, pipelined ---
__global__ __launch_bounds__(64) void scanA_kernel(
    const float* __restrict__ Dp, const float* __restrict__ cw,
    const float* __restrict__ cb)
{
    const int blk = blockIdx.x;
    const int bh  = blk / SEG;
    const int seg = blk % SEG;
    const int b = bh >> 3, h = bh & 7;
    const int p = threadIdx.x;
    const float Dh = Dp[h];

    const int c = h * HD + p;
    const float w0 = cw[c * 4 + 0], w1 = cw[c * 4 + 1];
    const float w2 = cw[c * 4 + 2], w3 = cw[c * 4 + 3];
    const float cbias = cb[c];
    const float* colz = g_zx + DINNER + c;

    float hs[DS];
#pragma unroll
    for (int n = 0; n < DS; n++) hs[n] = 0.f;
    float prod = 1.f;

    const size_t r0 = (size_t)b * LSEQ + seg * SLEN;
    float vm3 = 0.f, vm2 = 0.f, vm1 = 0.f;
    if (seg != 0) {
        vm3 = colz[(r0 - 3) * DIN];
        vm2 = colz[(r0 - 2) * DIN];
        vm1 = colz[(r0 - 1) * DIN];
    }

    float dav = g_da[r0 * NH + h];
    float dtv = g_dt[r0 * NH + h];
    float vz  = colz[r0 * DIN];
    const float* bp = g_xbc + r0 * CONVD + DINNER;
    float4 B0 = *(const float4*)(bp +  0), B1 = *(const float4*)(bp +  4);
    float4 B2 = *(const float4*)(bp +  8), B3 = *(const float4*)(bp + 12);
    float4 C0 = *(const float4*)(bp + 16), C1 = *(const float4*)(bp + 20);
    float4 C2 = *(const float4*)(bp + 24), C3 = *(const float4*)(bp + 28);

    for (int l = 0; l < SLEN; l++) {
        const size_t r = r0 + l;
        float dav_n = dav, dtv_n = dtv, vz_n = vz;
        float4 nB0 = B0, nB1 = B1, nB2 = B2, nB3 = B3;
        float4 nC0 = C0, nC1 = C1, nC2 = C2, nC3 = C3;
        if (l + 1 < SLEN) {
            const size_t rn = r + 1;
            dav_n = g_da[rn * NH + h];
            dtv_n = g_dt[rn * NH + h];
            vz_n  = colz[rn * DIN];
            const float* bpn = g_xbc + rn * CONVD + DINNER;
            nB0 = *(const float4*)(bpn +  0); nB1 = *(const float4*)(bpn +  4);
            nB2 = *(const float4*)(bpn +  8); nB3 = *(const float4*)(bpn + 12);
            nC0 = *(const float4*)(bpn + 16); nC1 = *(const float4*)(bpn + 20);
            nC2 = *(const float4*)(bpn + 24); nC3 = *(const float4*)(bpn + 28);
        }

        prod *= dav;
        float ca = cbias + w3 * vz + w2 * vm1 + w1 * vm2 + w0 * vm3;
        float xv = ca * fsig(ca);
        vm3 = vm2; vm2 = vm1; vm1 = vz;

        float bb[DS] = {B0.x,B0.y,B0.z,B0.w, B1.x,B1.y,B1.z,B1.w,
                        B2.x,B2.y,B2.z,B2.w, B3.x,B3.y,B3.z,B3.w};
        float cc[DS] = {C0.x,C0.y,C0.z,C0.w, C1.x,C1.y,C1.z,C1.w,
                        C2.x,C2.y,C2.z,C2.w, C3.x,C3.y,C3.z,C3.w};

        float t1 = dtv * xv;
        float yv0 = 0.f, yv1 = 0.f;
#pragma unroll
        for (int n = 0; n < DS; n += 2) {
            hs[n]   = fmaf(dav, hs[n],   t1 * bb[n]);
            hs[n+1] = fmaf(dav, hs[n+1], t1 * bb[n+1]);
            yv0 = fmaf(hs[n],   cc[n],   yv0);
            yv1 = fmaf(hs[n+1], cc[n+1], yv1);
        }
        g_y[r * DINNER + h * HD + p] = yv0 + yv1 + Dh * xv;

        dav = dav_n; dtv = dtv_n; vz = vz_n;
        B0 = nB0; B1 = nB1; B2 = nB2; B3 = nB3;
        C0 = nC0; C1 = nC1; C2 = nC2; C3 = nC3;
    }

    float* he = g_hend + ((size_t)bh * SEG + seg) * STATE + p * DS;
#pragma unroll
    for (int n = 0; n < DS; n += 4)
        *(float4*)(he + n) = make_float4(hs[n], hs[n+1], hs[n+2], hs[n+3]);
    if (p == 0) g_P[(size_t)bh * SEG + seg] = prod;
}

// ---------------- kernel 5b: compose segment states ----------------
__global__ __launch_bounds__(1024) void scanB_kernel()
{
    const int bh = blockIdx.x;
    const int pn = threadIdx.x;
    __shared__ float sP[SEG];
    if (pn < SEG) sP[pn] = g_P[(size_t)bh * SEG + pn];
    __syncthreads();

    float h = 0.f;
    const size_t base = (size_t)bh * SEG * STATE + pn;
    for (int seg = 0; seg < SEG; seg++) {
        g_hin[base + (size_t)seg * STATE] = h;
        h = fmaf(sP[seg], h, g_hend[base + (size_t)seg * STATE]);
    }
}

// ---------------- kernel 5c: cross-segment correction, pipelined ---------
__global__ __launch_bounds__(64) void scanC_kernel()
{
    const int blk = blockIdx.x;
    const int bh  = blk / (SEG - 1);
    const int seg = blk % (SEG - 1) + 1;
    const int b = bh >> 3, h = bh & 7;
    const int p = threadIdx.x;

    float hi[DS];
    const float* hp = g_hin + ((size_t)bh * SEG + seg) * STATE + p * DS;
#pragma unroll
    for (int n = 0; n < DS; n += 4) {
        float4 v = *(const float4*)(hp + n);
        hi[n] = v.x; hi[n+1] = v.y; hi[n+2] = v.z; hi[n+3] = v.w;
    }

    float cp = 1.f;
    const size_t r0 = (size_t)b * LSEQ + seg * SLEN;

    float dav = g_da[r0 * NH + h];
    const float* bp0 = g_xbc + r0 * CONVD + DINNER;
    float4 C0 = *(const float4*)(bp0 + 16), C1 = *(const float4*)(bp0 + 20);
    float4 C2 = *(const float4*)(bp0 + 24), C3 = *(const float4*)(bp0 + 28);

    for (int l = 0; l < SLEN; l++) {
        const size_t r = r0 + l;
        float dav_n = dav;
        float4 nC0 = C0, nC1 = C1, nC2 = C2, nC3 = C3;
        if (l + 1 < SLEN) {
            const size_t rn = r + 1;
            dav_n = g_da[rn * NH + h];
            const float* bpn = g_xbc + rn * CONVD + DINNER;
            nC0 = *(const float4*)(bpn + 16); nC1 = *(const float4*)(bpn + 20);
            nC2 = *(const float4*)(bpn + 24); nC3 = *(const float4*)(bpn + 28);
        }

        cp *= dav;
        float cc[DS] = {C0.x,C0.y,C0.z,C0.w, C1.x,C1.y,C1.z,C1.w,
                        C2.x,C2.y,C2.z,C2.w, C3.x,C3.y,C3.z,C3.w};
        float d0 = 0.f, d1 = 0.f;
#pragma unroll
        for (int n = 0; n < DS; n += 2) {
            d0 = fmaf(hi[n],   cc[n],   d0);
            d1 = fmaf(hi[n+1], cc[n+1], d1);
        }
        g_y[r * DINNER + h * HD + p] += cp * (d0 + d1);

        dav = dav_n;
        C0 = nC0; C1 = nC1; C2 = nC2; C3 = nC3;
    }
}

// ---------------- GEMM2 fused, pipelined (R7): gate + RMSNorm +
// out_proj + transpose + residual.
#define G2_ASTRIDE 36
#define G2_BSTRIDE 264
#define G2_BSZ (32*G2_BSTRIDE)
#define G2_POOLF (64*G2_ASTRIDE + 2*G2_BSZ)    // 19200 floats
#define SMEM_G2 (G2_POOLF*4)                   // 76800 bytes

__global__ __launch_bounds__(256) void gemm2_fused_kernel(
    const float* __restrict__ x, float* __restrict__ out)
{
    extern __shared__ float pool[];
    float* As = pool;                   // [64][36]
    float* Bs = pool + 64 * G2_ASTRIDE; // [2][32][264]
    const int t = threadIdx.x;
    const int warp = t >> 5, lane = t & 31;
    const int wm = warp & 1, wn = warp >> 1;
    const int m0 = blockIdx.x * 64;
    const int g = lane >> 2, tg = lane & 3;
    const int r0 = t >> 3, kc0 = (t & 7) << 2;

    float acc[2][8][4];
#pragma unroll
    for (int mi = 0; mi < 2; mi++)
#pragma unroll
        for (int nj = 0; nj < 8; nj++)
#pragma unroll
            for (int q = 0; q < 4; q++) acc[mi][nj][q] = 0.f;
    float sq0 = 0.f, sq1 = 0.f;

    auto issueB = [&](int k0, int buf) {
        float* Bsb = Bs + buf * G2_BSZ;
        const float* Wg = g_wouts + (size_t)k0 * CCH;
#pragma unroll
        for (int i = 0; i < 8; i++) {
            int idx = t + i * 256;
            int kr = idx >> 6, nc = (idx & 63) << 2;
            cp16(Bsb + kr * G2_BSTRIDE + nc, Wg + (size_t)kr * CCH + nc);
        }
    };

    issueB(0, 0);
    CP_COMMIT();
    float4 ry0, ry1, rz0, rz1;
    {
        size_t rra = (size_t)(m0 + r0);
        size_t rrb = (size_t)(m0 + r0 + 32);
        ry0 = *(const float4*)(g_y  + rra * DINNER + kc0);
        rz0 = *(const float4*)(g_zx + rra * DIN    + kc0);
        ry1 = *(const float4*)(g_y  + rrb * DINNER + kc0);
        rz1 = *(const float4*)(g_zx + rrb * DIN    + kc0);
    }

    const int NT = DINNER / 32;   // 16
    for (int kt = 0; kt < NT; kt++) {
        {
            float v0 = ry0.x * (rz0.x * fsig(rz0.x));
            float v1 = ry0.y * (rz0.y * fsig(rz0.y));
            float v2 = ry0.z * (rz0.z * fsig(rz0.z));
            float v3 = ry0.w * (rz0.w * fsig(rz0.w));
            As[r0 * G2_ASTRIDE + kc0 + 0] = __uint_as_float(f2tf32(v0));
            As[r0 * G2_ASTRIDE + kc0 + 1] = __uint_as_float(f2tf32(v1));
            As[r0 * G2_ASTRIDE + kc0 + 2] = __uint_as_float(f2tf32(v2));
            As[r0 * G2_ASTRIDE + kc0 + 3] = __uint_as_float(f2tf32(v3));
            sq0 += v0*v0 + v1*v1 + v2*v2 + v3*v3;
            float u0 = ry1.x * (rz1.x * fsig(rz1.x));
            float u1 = ry1.y * (rz1.y * fsig(rz1.y));
            float u2 = ry1.z * (rz1.z * fsig(rz1.z));
            float u3 = ry1.w * (rz1.w * fsig(rz1.w));
            As[(r0 + 32) * G2_ASTRIDE + kc0 + 0] = __uint_as_float(f2tf32(u0));
            As[(r0 + 32) * G2_ASTRIDE + kc0 + 1] = __uint_as_float(f2tf32(u1));
            As[(r0 + 32) * G2_ASTRIDE + kc0 + 2] = __uint_as_float(f2tf32(u2));
            As[(r0 + 32) * G2_ASTRIDE + kc0 + 3] = __uint_as_float(f2tf32(u3));
            sq1 += u0*u0 + u1*u1 + u2*u2 + u3*u3;
        }
        if (kt + 1 < NT) {
            issueB((kt + 1) * 32, (kt + 1) & 1);
            CP_COMMIT();
            int k1 = (kt + 1) * 32 + kc0;
            size_t rra = (size_t)(m0 + r0);
            size_t rrb = (size_t)(m0 + r0 + 32);
            ry0 = *(const float4*)(g_y  + rra * DINNER + k1);
            rz0 = *(const float4*)(g_zx + rra * DIN    + k1);
            ry1 = *(const float4*)(g_y  + rrb * DINNER + k1);
            rz1 = *(const float4*)(g_zx + rrb * DIN    + k1);
            CP_WAIT1();
        } else {
            CP_WAIT0();
        }
        __syncthreads();

        const float* Bsb = Bs + (kt & 1) * G2_BSZ;
#pragma unroll
        for (int kk = 0; kk < 32; kk += 8) {
            uint32_t af[2][4];
#pragma unroll
            for (int mi = 0; mi < 2; mi++) {
                int mb = wm * 32 + mi * 16;
                af[mi][0] = __float_as_uint(As[(mb + g    ) * G2_ASTRIDE + kk + tg]);
                af[mi][1] = __float_as_uint(As[(mb + 8 + g) * G2_ASTRIDE + kk + tg]);
                af[mi][2] = __float_as_uint(As[(mb + g    ) * G2_ASTRIDE + kk + 4 + tg]);
                af[mi][3] = __float_as_uint(As[(mb + 8 + g) * G2_ASTRIDE + kk + 4 + tg]);
            }
            uint32_t bf[8][2];
#pragma unroll
            for (int nj = 0; nj < 8; nj++) {
                int nb = wn * 64 + nj * 8;
                bf[nj][0] = __float_as_uint(Bsb[(kk + tg    ) * G2_BSTRIDE + nb + g]);
                bf[nj][1] = __float_as_uint(Bsb[(kk + 4 + tg) * G2_BSTRIDE + nb + g]);
            }
#pragma unroll
            for (int mi = 0; mi < 2; mi++)
#pragma unroll
                for (int nj = 0; nj < 8; nj++) MMA_TF32(acc[mi][nj], af[mi], bf[nj]);
        }
        __syncthreads();
    }

    // rn reduction
    float* sq = pool;
    sq[r0 * 8 + (t & 7)] = sq0;
    sq[(r0 + 32) * 8 + (t & 7)] = sq1;
    __syncthreads();
    float* rn = pool + 512;
    if (t < 64) {
        float s = 0.f;
#pragma unroll
        for (int j = 0; j < 8; j++) s += sq[t * 8 + j];
        rn[t] = rsqrtf(s * (1.f / (float)DINNER) + EPS);
    }
    __syncthreads();
    float rsc[2][2];
#pragma unroll
    for (int mi = 0; mi < 2; mi++) {
        rsc[mi][0] = rn[wm * 32 + mi * 16 + g];
        rsc[mi][1] = rn[wm * 32 + mi * 16 + 8 + g];
    }
    __syncthreads();

    // epilogue: transpose + residual
    float* epi = pool;
    const int b  = m0 >> 12;
    const int l0 = m0 & (LSEQ - 1);
#pragma unroll
    for (int cj = 0; cj < 4; cj++) {
        if (wn == cj) {
#pragma unroll
            for (int mi = 0; mi < 2; mi++)
#pragma unroll
                for (int nj = 0; nj < 8; nj++)
#pragma unroll
                    for (int q = 0; q < 4; q++) {
                        int Rl = wm * 32 + mi * 16 + g + ((q >> 1) << 3);
                        int cl = nj * 8 + 2 * tg + (q & 1);
                        epi[cl * 68 + Rl] = acc[mi][nj][q] * rsc[mi][q >> 1];
                    }
        }
        __syncthreads();
        {
            int c = t >> 2, sg2 = t & 3;
            size_t ob = ((size_t)b * CCH + cj * 64 + c) * LSEQ + l0 + sg2 * 16;
#pragma unroll
            for (int j = 0; j < 4; j++) {
                float4 e  = *(float4*)(epi + c * 68 + sg2 * 16 + j * 4);
                float4 xr = *(const float4*)(x + ob + j * 4);
                e.x += xr.x; e.y += xr.y; e.z += xr.z; e.w += xr.w;
                *(float4*)(out + ob + j * 4) = e;
            }
        }
        __syncthreads();
    }
}

extern "C" void kernel_launch(void* const* d_in, const int* in_sizes, int n_in,
                              void* d_out, int out_size)
{
    const float* x       = (const float*)d_in[0];
    const float* ln_g    = (const float*)d_in[1];
    const float* ln_b    = (const float*)d_in[2];
    const float* Win     = (const float*)d_in[3];
    const float* Wout    = (const float*)d_in[4];
    const float* conv_w  = (const float*)d_in[5];
    const float* conv_b  = (const float*)d_in[6];
    const float* dt_bias = (const float*)d_in[7];
    const float* A_log   = (const float*)d_in[8];
    const float* Dp      = (const float*)d_in[9];
    const float* rms_w   = (const float*)d_in[10];
    float* out = (float*)d_out;

    cudaFuncSetAttribute(gemm1_kernel,
                         cudaFuncAttributeMaxDynamicSharedMemorySize, SMEM_G1);
    cudaFuncSetAttribute(gemm2_fused_kernel,
                         cudaFuncAttributeMaxDynamicSharedMemorySize, SMEM_G2);

    // 0) precompute TF32 weights
    prep_kernel<<<(CCH * DIN + 255) / 256, 256>>>(Win, Wout, rms_w);

    // 1) LN stats
    stats_kernel<<<dim3(LSEQ / 32, BATCH), 256>>>(x);

    // 2) in_proj GEMM: LN applied at fragment-read; dt/dA in epilogue
    gemm1_kernel<<<dim3((DIN + 127) / 128, ROWS / 128), 256, SMEM_G1>>>(
        x, ln_g, ln_b, dt_bias, A_log);

    // 3) conv + silu, B/C channels only
    convbc_kernel<<<((ROWS / TROW) * NBC + 255) / 256, 256>>>(conv_w, conv_b);

    // 4) segmented SSM scan (x-conv fused into scanA)
    scanA_kernel<<<NBH * SEG, HD>>>(Dp, conv_w, conv_b);
    scanB_kernel<<<NBH, STATE>>>();
    scanC_kernel<<<NBH * (SEG - 1), HD>>>();

    // 5) fused pipelined: gate + rmsnorm + out_proj + transpose + residual (R7)
    gemm2_fused_kernel<<<ROWS / 64, 256, SMEM_G2>>>(x, out);
}

// round 13
// speedup vs baseline: 1.3918x; 1.0539x over previous
#include <cuda_runtime.h>
#include <cuda_bf16.h>
#include <math.h>
#include <stdint.h>

// ---------------- problem constants ----------------
#define BATCH   8
#define CCH     256
#define LSEQ    4096
#define ROWS    (BATCH*LSEQ)   // 32768
#define DIN     1064
#define DINNER  512
#define NH      8
#define HD      64
#define DS      16
#define EPS     1e-5f

#define SEG     64
#define SLEN    (LSEQ/SEG)
#define NBH     (BATCH*NH)
#define STATE   (HD*DS)

// ---------------- scratch ----------------
__device__ float g_un [(size_t)ROWS*CCH];       // TF32-rounded LN output
__device__ float g_win[(size_t)CCH*DIN];        // TF32-rounded Win
__device__ float g_wouts[(size_t)DINNER*CCH];   // TF32-rounded Wout*rms_w
__device__ float g_zx [(size_t)ROWS*DIN];
__device__ float g_bc [(size_t)ROWS*32];        // compact conv(B,C) output
__device__ float g_dt [(size_t)ROWS*NH];
__device__ float g_da [(size_t)ROWS*NH];
__device__ float g_y  [(size_t)ROWS*DINNER];
__device__ float g_hend[(size_t)NBH*SEG*STATE];
__device__ float g_hin [(size_t)NBH*SEG*STATE];
__device__ float g_P   [(size_t)NBH*SEG];

// ---------------- helpers ----------------
__device__ __forceinline__ uint32_t f2tf32(float f) {
    uint32_t r;
    asm("cvt.rna.tf32.f32 %0, %1;" : "=r"(r) : "f"(f));
    return r;
}
__device__ __forceinline__ float fsig(float v) {
    return __fdividef(1.f, 1.f + __expf(-v));
}
__device__ __forceinline__ void cp16(float* s, const float* g) {
    uint32_t sa = (uint32_t)__cvta_generic_to_shared(s);
    asm volatile("cp.async.cg.shared.global [%0], [%1], 16;" :: "r"(sa), "l"(g));
}
__device__ __forceinline__ void cp8z(float* s, const float* g, bool p) {
    uint32_t sa = (uint32_t)__cvta_generic_to_shared(s);
    int sz = p ? 8 : 0;
    asm volatile("cp.async.ca.shared.global [%0], [%1], 8, %2;" :: "r"(sa), "l"(g), "r"(sz));
}
#define CP_COMMIT() asm volatile("cp.async.commit_group;")
#define CP_WAIT1()  asm volatile("cp.async.wait_group 1;")
#define CP_WAIT0()  asm volatile("cp.async.wait_group 0;")

#define MMA_TF32(acc, af, bf) \
    asm volatile( \
        "mma.sync.aligned.m16n8k8.row.col.f32.tf32.tf32.f32 " \
        "{%0,%1,%2,%3}, {%4,%5,%6,%7}, {%8,%9}, {%0,%1,%2,%3};" \
        : "+f"(acc[0]), "+f"(acc[1]), "+f"(acc[2]), "+f"(acc[3]) \
        : "r"(af[0]), "r"(af[1]), "r"(af[2]), "r"(af[3]), "r"(bf[0]), "r"(bf[1]))

// ---------------- kernel 0: precompute TF32 weights ----------------
__global__ void prep_kernel(const float* __restrict__ Win,
                            const float* __restrict__ Wout,
                            const float* __restrict__ rms_w)
{
    int i = blockIdx.x * 256 + threadIdx.x;
    if (i < CCH * DIN) g_win[i] = __uint_as_float(f2tf32(Win[i]));
    if (i < DINNER * CCH) {
        int k = i >> 8;
        g_wouts[i] = __uint_as_float(f2tf32(Wout[i] * rms_w[k]));
    }
}

// ---------------- kernel 1: layernorm (writes TF32-rounded un) ----------
__global__ __launch_bounds__(256) void ln_kernel(
    const float* __restrict__ x, const float* __restrict__ gamma,
    const float* __restrict__ beta)
{
    __shared__ float s[256][33];
    __shared__ float s_mu[32], s_rs[32];
    const int b  = blockIdx.y;
    const int l0 = blockIdx.x * 32;
    const int t  = threadIdx.x;

#pragma unroll
    for (int i = 0; i < 32; i++) {
        int flat = i * 256 + t;
        int c  = flat >> 5;
        int lp = flat & 31;
        s[c][lp] = x[((size_t)b * CCH + c) * LSEQ + l0 + lp];
    }
    __syncthreads();

    const int wid = t >> 5, lane = t & 31;
    for (int j = wid; j < 32; j += 8) {
        float v = 0.f, v2 = 0.f;
#pragma unroll
        for (int k = 0; k < 8; k++) {
            float a = s[lane + 32 * k][j];
            v += a; v2 += a * a;
        }
#pragma unroll
        for (int o = 16; o; o >>= 1) {
            v  += __shfl_xor_sync(0xffffffffu, v,  o);
            v2 += __shfl_xor_sync(0xffffffffu, v2, o);
        }
        if (lane == 0) {
            float m = v * (1.f / 256.f);
            s_mu[j] = m;
            s_rs[j] = rsqrtf(v2 * (1.f / 256.f) - m * m + EPS);
        }
    }
    __syncthreads();

#pragma unroll
    for (int i = 0; i < 32; i++) {
        int flat = i * 256 + t;
        int lp = flat >> 8;
        int c  = flat & 255;
        float v = (s[c][lp] - s_mu[lp]) * s_rs[lp] * gamma[c] + beta[c];
        g_un[((size_t)b * LSEQ + l0 + lp) * CCH + c] = __uint_as_float(f2tf32(v));
    }
}

// ---------------- GEMM1: zx = un @ win, TF32, cp.async 2-stage ----------
// dt/dA fused in epilogue (n-block 8 holds dt cols).
#define G1_ASTRIDE 36
#define G1_BSTRIDE 136
#define G1_ASZ (128*G1_ASTRIDE)
#define G1_BSZ (32*G1_BSTRIDE)
#define SMEM_G1 ((2*G1_ASZ + 2*G1_BSZ)*4)   // 71680 bytes

__global__ __launch_bounds__(256) void gemm1_kernel(
    const float* __restrict__ dt_bias, const float* __restrict__ A_log)
{
    extern __shared__ float dsm[];
    float* As = dsm;
    float* Bs = dsm + 2*G1_ASZ;
    const int t = threadIdx.x;
    const int warp = t >> 5, lane = t & 31;
    const int wm = warp & 3, wn = warp >> 2;
    const int m0 = blockIdx.y * 128;
    const int n0 = blockIdx.x * 128;
    const int g = lane >> 2, tg = lane & 3;
    const int N = DIN, K = CCH;

    float acc[2][8][4];
#pragma unroll
    for (int mi = 0; mi < 2; mi++)
#pragma unroll
        for (int nj = 0; nj < 8; nj++)
#pragma unroll
            for (int q = 0; q < 4; q++) acc[mi][nj][q] = 0.f;

    auto issue = [&](int tile, int buf) {
        const float* Ag = g_un + (size_t)m0 * K + tile * 32;
        float* Asb = As + buf * G1_ASZ;
#pragma unroll
        for (int i = 0; i < 4; i++) {
            int idx = t + i * 256;
            int row = idx >> 3, kc = (idx & 7) << 2;
            cp16(Asb + row * G1_ASTRIDE + kc, Ag + (size_t)row * K + kc);
        }
        const float* Bg = g_win + (size_t)(tile * 32) * N + n0;
        float* Bsb = Bs + buf * G1_BSZ;
#pragma unroll
        for (int i = 0; i < 8; i++) {
            int idx = t + i * 256;
            int kr = idx >> 6, nc = (idx & 63) << 1;
            cp8z(Bsb + kr * G1_BSTRIDE + nc, Bg + (size_t)kr * N + nc, n0 + nc < N);
        }
    };

    const int T = K / 32;   // 8
    issue(0, 0);
    CP_COMMIT();
    for (int i = 0; i < T; i++) {
        if (i + 1 < T) issue(i + 1, (i + 1) & 1);
        CP_COMMIT();
        CP_WAIT1();
        __syncthreads();
        const float* Asb = As + (i & 1) * G1_ASZ;
        const float* Bsb = Bs + (i & 1) * G1_BSZ;
#pragma unroll
        for (int kk = 0; kk < 32; kk += 8) {
            uint32_t af[2][4];
#pragma unroll
            for (int mi = 0; mi < 2; mi++) {
                int mb = wm * 32 + mi * 16;
                af[mi][0] = __float_as_uint(Asb[(mb + g    ) * G1_ASTRIDE + kk + tg]);
                af[mi][1] = __float_as_uint(Asb[(mb + 8 + g) * G1_ASTRIDE + kk + tg]);
                af[mi][2] = __float_as_uint(Asb[(mb + g    ) * G1_ASTRIDE + kk + 4 + tg]);
                af[mi][3] = __float_as_uint(Asb[(mb + 8 + g) * G1_ASTRIDE + kk + 4 + tg]);
            }
            uint32_t bf[8][2];
#pragma unroll
            for (int nj = 0; nj < 8; nj++) {
                int nb = wn * 64 + nj * 8;
                bf[nj][0] = __float_as_uint(Bsb[(kk + tg    ) * G1_BSTRIDE + nb + g]);
                bf[nj][1] = __float_as_uint(Bsb[(kk + 4 + tg) * G1_BSTRIDE + nb + g]);
            }
#pragma unroll
            for (int mi = 0; mi < 2; mi++)
#pragma unroll
                for (int nj = 0; nj < 8; nj++) MMA_TF32(acc[mi][nj], af[mi], bf[nj]);
        }
        __syncthreads();
    }

#pragma unroll
    for (int mi = 0; mi < 2; mi++) {
        int rbase = m0 + wm * 32 + mi * 16 + g;
#pragma unroll
        for (int nj = 0; nj < 8; nj++) {
            int col = n0 + wn * 64 + nj * 8 + 2 * tg;
            if (col < N) {
                *(float2*)(g_zx + (size_t)rbase * N + col) =
                    make_float2(acc[mi][nj][0], acc[mi][nj][1]);
                *(float2*)(g_zx + (size_t)(rbase + 8) * N + col) =
                    make_float2(acc[mi][nj][2], acc[mi][nj][3]);
            }
        }
    }
    // fused dt/dA: dt cols 1056..1063 -> n-block 8, wn==0, nj==4
    if (blockIdx.x == 8 && wn == 0) {
#pragma unroll
        for (int mi = 0; mi < 2; mi++) {
            int rb_ = m0 + wm * 32 + mi * 16 + g;
#pragma unroll
            for (int q = 0; q < 4; q++) {
                int h = 2 * tg + (q & 1);
                int row = rb_ + ((q >> 1) << 3);
                float v = acc[mi][4][q] + dt_bias[h];
                float d = (v > 20.f) ? v : log1pf(__expf(v));
                float Ah = -__expf(A_log[h]);
                g_dt[(size_t)row * NH + h] = d;
                g_da[(size_t)row * NH + h] = __expf(d * Ah);
            }
        }
    }
}

// ---------------- kernel 4: conv(4)+SiLU, B/C channels -> compact g_bc ----
#define TROW 8
#define NBC  32
__global__ void convbc_kernel(const float* __restrict__ cw,
                              const float* __restrict__ cb)
{
    int id = blockIdx.x * blockDim.x + threadIdx.x;
    if (id >= (ROWS / TROW) * NBC) return;
    int cl = id % NBC;                // 0..31
    int c  = DINNER + cl;             // 512..543
    int rb = id / NBC;
    int r0 = rb * TROW;
    int l0 = r0 & (LSEQ - 1);

    const float* col = g_zx + DINNER + c;
    float w0 = cw[c * 4 + 0], w1 = cw[c * 4 + 1];
    float w2 = cw[c * 4 + 2], w3 = cw[c * 4 + 3];
    float bias = cb[c];

    float vm3 = 0.f, vm2 = 0.f, vm1 = 0.f;
    if (l0 != 0) {
        vm3 = col[(size_t)(r0 - 3) * DIN];
        vm2 = col[(size_t)(r0 - 2) * DIN];
        vm1 = col[(size_t)(r0 - 1) * DIN];
    }
#pragma unroll
    for (int i = 0; i < TROW; i++) {
        float v = col[(size_t)(r0 + i) * DIN];
        float acc = bias + w3 * v + w2 * vm1 + w1 * vm2 + w0 * vm3;
        g_bc[(size_t)(r0 + i) * 32 + cl] = acc * fsig(acc);
        vm3 = vm2; vm2 = vm1; vm1 = v;
    }
}

// ---------------- kernel 5a: segment-local scan, fused x-conv, pipelined ---
__global__ __launch_bounds__(64) void scanA_kernel(
    const float* __restrict__ Dp, const float* __restrict__ cw,
    const float* __restrict__ cb)
{
    const int blk = blockIdx.x;
    const int bh  = blk / SEG;
    const int seg = blk % SEG;
    const int b = bh >> 3, h = bh & 7;
    const int p = threadIdx.x;
    const float Dh = Dp[h];

    const int c = h * HD + p;
    const float w0 = cw[c * 4 + 0], w1 = cw[c * 4 + 1];
    const float w2 = cw[c * 4 + 2], w3 = cw[c * 4 + 3];
    const float cbias = cb[c];
    const float* colz = g_zx + DINNER + c;

    float hs[DS];
#pragma unroll
    for (int n = 0; n < DS; n++) hs[n] = 0.f;
    float prod = 1.f;

    const size_t r0 = (size_t)b * LSEQ + seg * SLEN;
    float vm3 = 0.f, vm2 = 0.f, vm1 = 0.f;
    if (seg != 0) {
        vm3 = colz[(r0 - 3) * DIN];
        vm2 = colz[(r0 - 2) * DIN];
        vm1 = colz[(r0 - 1) * DIN];
    }

    float dav = g_da[r0 * NH + h];
    float dtv = g_dt[r0 * NH + h];
    float vz  = colz[r0 * DIN];
    const float* bp = g_bc + r0 * 32;
    float4 B0 = *(const float4*)(bp +  0), B1 = *(const float4*)(bp +  4);
    float4 B2 = *(const float4*)(bp +  8), B3 = *(const float4*)(bp + 12);
    float4 C0 = *(const float4*)(bp + 16), C1 = *(const float4*)(bp + 20);
    float4 C2 = *(const float4*)(bp + 24), C3 = *(const float4*)(bp + 28);

    for (int l = 0; l < SLEN; l++) {
        const size_t r = r0 + l;
        float dav_n = dav, dtv_n = dtv, vz_n = vz;
        float4 nB0 = B0, nB1 = B1, nB2 = B2, nB3 = B3;
        float4 nC0 = C0, nC1 = C1, nC2 = C2, nC3 = C3;
        if (l + 1 < SLEN) {
            const size_t rn = r + 1;
            dav_n = g_da[rn * NH + h];
            dtv_n = g_dt[rn * NH + h];
            vz_n  = colz[rn * DIN];
            const float* bpn = g_bc + rn * 32;
            nB0 = *(const float4*)(bpn +  0); nB1 = *(const float4*)(bpn +  4);
            nB2 = *(const float4*)(bpn +  8); nB3 = *(const float4*)(bpn + 12);
            nC0 = *(const float4*)(bpn + 16); nC1 = *(const float4*)(bpn + 20);
            nC2 = *(const float4*)(bpn + 24); nC3 = *(const float4*)(bpn + 28);
        }

        prod *= dav;
        float ca = cbias + w3 * vz + w2 * vm1 + w1 * vm2 + w0 * vm3;
        float xv = ca * fsig(ca);
        vm3 = vm2; vm2 = vm1; vm1 = vz;

        float bb[DS] = {B0.x,B0.y,B0.z,B0.w, B1.x,B1.y,B1.z,B1.w,
                        B2.x,B2.y,B2.z,B2.w, B3.x,B3.y,B3.z,B3.w};
        float cc[DS] = {C0.x,C0.y,C0.z,C0.w, C1.x,C1.y,C1.z,C1.w,
                        C2.x,C2.y,C2.z,C2.w, C3.x,C3.y,C3.z,C3.w};

        float t1 = dtv * xv;
        float yv0 = 0.f, yv1 = 0.f;
#pragma unroll
        for (int n = 0; n < DS; n += 2) {
            hs[n]   = fmaf(dav, hs[n],   t1 * bb[n]);
            hs[n+1] = fmaf(dav, hs[n+1], t1 * bb[n+1]);
            yv0 = fmaf(hs[n],   cc[n],   yv0);
            yv1 = fmaf(hs[n+1], cc[n+1], yv1);
        }
        g_y[r * DINNER + h * HD + p] = yv0 + yv1 + Dh * xv;

        dav = dav_n; dtv = dtv_n; vz = vz_n;
        B0 = nB0; B1 = nB1; B2 = nB2; B3 = nB3;
        C0 = nC0; C1 = nC1; C2 = nC2; C3 = nC3;
    }

    float* he = g_hend + ((size_t)bh * SEG + seg) * STATE + p * DS;
#pragma unroll
    for (int n = 0; n < DS; n += 4)
        *(float4*)(he + n) = make_float4(hs[n], hs[n+1], hs[n+2], hs[n+3]);
    if (p == 0) g_P[(size_t)bh * SEG + seg] = prod;
}

// ---------------- kernel 5b: compose segment states (128 blocks) ---------
__global__ __launch_bounds__(512) void scanB_kernel()
{
    const int blk = blockIdx.x;
    const int bh = blk >> 1;
    const int pn = (blk & 1) * 512 + threadIdx.x;
    __shared__ float sP[SEG];
    if (threadIdx.x < SEG) sP[threadIdx.x] = g_P[(size_t)bh * SEG + threadIdx.x];
    __syncthreads();

    float h = 0.f;
    const size_t base = (size_t)bh * SEG * STATE + pn;
    for (int seg = 0; seg < SEG; seg++) {
        g_hin[base + (size_t)seg * STATE] = h;
        h = fmaf(sP[seg], h, g_hend[base + (size_t)seg * STATE]);
    }
}

// ---------------- kernel 5c: cross-segment correction, pipelined ---------
__global__ __launch_bounds__(64) void scanC_kernel()
{
    const int blk = blockIdx.x;
    const int bh  = blk / (SEG - 1);
    const int seg = blk % (SEG - 1) + 1;
    const int b = bh >> 3, h = bh & 7;
    const int p = threadIdx.x;

    float hi[DS];
    const float* hp = g_hin + ((size_t)bh * SEG + seg) * STATE + p * DS;
#pragma unroll
    for (int n = 0; n < DS; n += 4) {
        float4 v = *(const float4*)(hp + n);
        hi[n] = v.x; hi[n+1] = v.y; hi[n+2] = v.z; hi[n+3] = v.w;
    }

    float cp = 1.f;
    const size_t r0 = (size_t)b * LSEQ + seg * SLEN;

    float dav = g_da[r0 * NH + h];
    const float* bp0 = g_bc + r0 * 32;
    float4 C0 = *(const float4*)(bp0 + 16), C1 = *(const float4*)(bp0 + 20);
    float4 C2 = *(const float4*)(bp0 + 24), C3 = *(const float4*)(bp0 + 28);

    for (int l = 0; l < SLEN; l++) {
        const size_t r = r0 + l;
        float dav_n = dav;
        float4 nC0 = C0, nC1 = C1, nC2 = C2, nC3 = C3;
        if (l + 1 < SLEN) {
            const size_t rn = r + 1;
            dav_n = g_da[rn * NH + h];
            const float* bpn = g_bc + rn * 32;
            nC0 = *(const float4*)(bpn + 16); nC1 = *(const float4*)(bpn + 20);
            nC2 = *(const float4*)(bpn + 24); nC3 = *(const float4*)(bpn + 28);
        }

        cp *= dav;
        float cc[DS] = {C0.x,C0.y,C0.z,C0.w, C1.x,C1.y,C1.z,C1.w,
                        C2.x,C2.y,C2.z,C2.w, C3.x,C3.y,C3.z,C3.w};
        float d0 = 0.f, d1 = 0.f;
#pragma unroll
        for (int n = 0; n < DS; n += 2) {
            d0 = fmaf(hi[n],   cc[n],   d0);
            d1 = fmaf(hi[n+1], cc[n+1], d1);
        }
        g_y[r * DINNER + h * HD + p] += cp * (d0 + d1);

        dav = dav_n;
        C0 = nC0; C1 = nC1; C2 = nC2; C3 = nC3;
    }
}

// ---------------- GEMM2 fused, pipelined (R7): gate + RMSNorm +
// out_proj + transpose + residual.
#define G2_ASTRIDE 36
#define G2_BSTRIDE 264
#define G2_BSZ (32*G2_BSTRIDE)
#define G2_POOLF (64*G2_ASTRIDE + 2*G2_BSZ)    // 19200 floats
#define SMEM_G2 (G2_POOLF*4)                   // 76800 bytes

__global__ __launch_bounds__(256) void gemm2_fused_kernel(
    const float* __restrict__ x, float* __restrict__ out)
{
    extern __shared__ float pool[];
    float* As = pool;                   // [64][36]
    float* Bs = pool + 64 * G2_ASTRIDE; // [2][32][264]
    const int t = threadIdx.x;
    const int warp = t >> 5, lane = t & 31;
    const int wm = warp & 1, wn = warp >> 1;
    const int m0 = blockIdx.x * 64;
    const int g = lane >> 2, tg = lane & 3;
    const int r0 = t >> 3, kc0 = (t & 7) << 2;

    float acc[2][8][4];
#pragma unroll
    for (int mi = 0; mi < 2; mi++)
#pragma unroll
        for (int nj = 0; nj < 8; nj++)
#pragma unroll
            for (int q = 0; q < 4; q++) acc[mi][nj][q] = 0.f;
    float sq0 = 0.f, sq1 = 0.f;

    auto issueB = [&](int k0, int buf) {
        float* Bsb = Bs + buf * G2_BSZ;
        const float* Wg = g_wouts + (size_t)k0 * CCH;
#pragma unroll
        for (int i = 0; i < 8; i++) {
            int idx = t + i * 256;
            int kr = idx >> 6, nc = (idx & 63) << 2;
            cp16(Bsb + kr * G2_BSTRIDE + nc, Wg + (size_t)kr * CCH + nc);
        }
    };

    issueB(0, 0);
    CP_COMMIT();
    float4 ry0, ry1, rz0, rz1;
    {
        size_t rra = (size_t)(m0 + r0);
        size_t rrb = (size_t)(m0 + r0 + 32);
        ry0 = *(const float4*)(g_y  + rra * DINNER + kc0);
        rz0 = *(const float4*)(g_zx + rra * DIN    + kc0);
        ry1 = *(const float4*)(g_y  + rrb * DINNER + kc0);
        rz1 = *(const float4*)(g_zx + rrb * DIN    + kc0);
    }

    const int NT = DINNER / 32;   // 16
    for (int kt = 0; kt < NT; kt++) {
        {
            float v0 = ry0.x * (rz0.x * fsig(rz0.x));
            float v1 = ry0.y * (rz0.y * fsig(rz0.y));
            float v2 = ry0.z * (rz0.z * fsig(rz0.z));
            float v3 = ry0.w * (rz0.w * fsig(rz0.w));
            As[r0 * G2_ASTRIDE + kc0 + 0] = __uint_as_float(f2tf32(v0));
            As[r0 * G2_ASTRIDE + kc0 + 1] = __uint_as_float(f2tf32(v1));
            As[r0 * G2_ASTRIDE + kc0 + 2] = __uint_as_float(f2tf32(v2));
            As[r0 * G2_ASTRIDE + kc0 + 3] = __uint_as_float(f2tf32(v3));
            sq0 += v0*v0 + v1*v1 + v2*v2 + v3*v3;
            float u0 = ry1.x * (rz1.x * fsig(rz1.x));
            float u1 = ry1.y * (rz1.y * fsig(rz1.y));
            float u2 = ry1.z * (rz1.z * fsig(rz1.z));
            float u3 = ry1.w * (rz1.w * fsig(rz1.w));
            As[(r0 + 32) * G2_ASTRIDE + kc0 + 0] = __uint_as_float(f2tf32(u0));
            As[(r0 + 32) * G2_ASTRIDE + kc0 + 1] = __uint_as_float(f2tf32(u1));
            As[(r0 + 32) * G2_ASTRIDE + kc0 + 2] = __uint_as_float(f2tf32(u2));
            As[(r0 + 32) * G2_ASTRIDE + kc0 + 3] = __uint_as_float(f2tf32(u3));
            sq1 += u0*u0 + u1*u1 + u2*u2 + u3*u3;
        }
        if (kt + 1 < NT) {
            issueB((kt + 1) * 32, (kt + 1) & 1);
            CP_COMMIT();
            int k1 = (kt + 1) * 32 + kc0;
            size_t rra = (size_t)(m0 + r0);
            size_t rrb = (size_t)(m0 + r0 + 32);
            ry0 = *(const float4*)(g_y  + rra * DINNER + k1);
            rz0 = *(const float4*)(g_zx + rra * DIN    + k1);
            ry1 = *(const float4*)(g_y  + rrb * DINNER + k1);
            rz1 = *(const float4*)(g_zx + rrb * DIN    + k1);
            CP_WAIT1();
        } else {
            CP_WAIT0();
        }
        __syncthreads();

        const float* Bsb = Bs + (kt & 1) * G2_BSZ;
#pragma unroll
        for (int kk = 0; kk < 32; kk += 8) {
            uint32_t af[2][4];
#pragma unroll
            for (int mi = 0; mi < 2; mi++) {
                int mb = wm * 32 + mi * 16;
                af[mi][0] = __float_as_uint(As[(mb + g    ) * G2_ASTRIDE + kk + tg]);
                af[mi][1] = __float_as_uint(As[(mb + 8 + g) * G2_ASTRIDE + kk + tg]);
                af[mi][2] = __float_as_uint(As[(mb + g    ) * G2_ASTRIDE + kk + 4 + tg]);
                af[mi][3] = __float_as_uint(As[(mb + 8 + g) * G2_ASTRIDE + kk + 4 + tg]);
            }
            uint32_t bf[8][2];
#pragma unroll
            for (int nj = 0; nj < 8; nj++) {
                int nb = wn * 64 + nj * 8;
                bf[nj][0] = __float_as_uint(Bsb[(kk + tg    ) * G2_BSTRIDE + nb + g]);
                bf[nj][1] = __float_as_uint(Bsb[(kk + 4 + tg) * G2_BSTRIDE + nb + g]);
            }
#pragma unroll
            for (int mi = 0; mi < 2; mi++)
#pragma unroll
                for (int nj = 0; nj < 8; nj++) MMA_TF32(acc[mi][nj], af[mi], bf[nj]);
        }
        __syncthreads();
    }

    // rn reduction
    float* sq = pool;
    sq[r0 * 8 + (t & 7)] = sq0;
    sq[(r0 + 32) * 8 + (t & 7)] = sq1;
    __syncthreads();
    float* rn = pool + 512;
    if (t < 64) {
        float s = 0.f;
#pragma unroll
        for (int j = 0; j < 8; j++) s += sq[t * 8 + j];
        rn[t] = rsqrtf(s * (1.f / (float)DINNER) + EPS);
    }
    __syncthreads();
    float rsc[2][2];
#pragma unroll
    for (int mi = 0; mi < 2; mi++) {
        rsc[mi][0] = rn[wm * 32 + mi * 16 + g];
        rsc[mi][1] = rn[wm * 32 + mi * 16 + 8 + g];
    }
    __syncthreads();

    // epilogue: transpose + residual
    float* epi = pool;
    const int b  = m0 >> 12;
    const int l0 = m0 & (LSEQ - 1);
#pragma unroll
    for (int cj = 0; cj < 4; cj++) {
        if (wn == cj) {
#pragma unroll
            for (int mi = 0; mi < 2; mi++)
#pragma unroll
                for (int nj = 0; nj < 8; nj++)
#pragma unroll
                    for (int q = 0; q < 4; q++) {
                        int Rl = wm * 32 + mi * 16 + g + ((q >> 1) << 3);
                        int cl = nj * 8 + 2 * tg + (q & 1);
                        epi[cl * 68 + Rl] = acc[mi][nj][q] * rsc[mi][q >> 1];
                    }
        }
        __syncthreads();
        {
            int c = t >> 2, sg2 = t & 3;
            size_t ob = ((size_t)b * CCH + cj * 64 + c) * LSEQ + l0 + sg2 * 16;
#pragma unroll
            for (int j = 0; j < 4; j++) {
                float4 e  = *(float4*)(epi + c * 68 + sg2 * 16 + j * 4);
                float4 xr = *(const float4*)(x + ob + j * 4);
                e.x += xr.x; e.y += xr.y; e.z += xr.z; e.w += xr.w;
                *(float4*)(out + ob + j * 4) = e;
            }
        }
        __syncthreads();
    }
}

extern "C" void kernel_launch(void* const* d_in, const int* in_sizes, int n_in,
                              void* d_out, int out_size)
{
    const float* x       = (const float*)d_in[0];
    const float* ln_g    = (const float*)d_in[1];
    const float* ln_b    = (const float*)d_in[2];
    const float* Win     = (const float*)d_in[3];
    const float* Wout    = (const float*)d_in[4];
    const float* conv_w  = (const float*)d_in[5];
    const float* conv_b  = (const float*)d_in[6];
    const float* dt_bias = (const float*)d_in[7];
    const float* A_log   = (const float*)d_in[8];
    const float* Dp      = (const float*)d_in[9];
    const float* rms_w   = (const float*)d_in[10];
    float* out = (float*)d_out;

    cudaFuncSetAttribute(gemm1_kernel,
                         cudaFuncAttributeMaxDynamicSharedMemorySize, SMEM_G1);
    cudaFuncSetAttribute(gemm2_fused_kernel,
                         cudaFuncAttributeMaxDynamicSharedMemorySize, SMEM_G2);

    // 0) precompute TF32 weights
    prep_kernel<<<(CCH * DIN + 255) / 256, 256>>>(Win, Wout, rms_w);

    // 1) layernorm (writes pre-rounded un)
    ln_kernel<<<dim3(LSEQ / 32, BATCH), 256>>>(x, ln_g, ln_b);

    // 2) in_proj GEMM with dt/dA epilogue
    gemm1_kernel<<<dim3((DIN + 127) / 128, ROWS / 128), 256, SMEM_G1>>>(
        dt_bias, A_log);

    // 3) conv + silu, B/C channels -> compact g_bc
    convbc_kernel<<<((ROWS / TROW) * NBC + 255) / 256, 256>>>(conv_w, conv_b);

    // 4) segmented SSM scan (x-conv fused into scanA)
    scanA_kernel<<<NBH * SEG, HD>>>(Dp, conv_w, conv_b);
    scanB_kernel<<<NBH * 2, 512>>>();
    scanC_kernel<<<NBH * (SEG - 1), HD>>>();

    // 5) fused pipelined: gate + rmsnorm + out_proj + transpose + residual
    gemm2_fused_kernel<<<ROWS / 64, 256, SMEM_G2>>>(x, out);
}

// round 15
// speedup vs baseline: 1.4326x; 1.0293x over previous
#include <cuda_runtime.h>
#include <cuda_bf16.h>
#include <math.h>
#include <stdint.h>

// ---------------- problem constants ----------------
#define BATCH   8
#define CCH     256
#define LSEQ    4096
#define ROWS    (BATCH*LSEQ)   // 32768
#define DIN     1064
#define DINNER  512
#define NH      8
#define HD      64
#define DS      16
#define EPS     1e-5f

#define SEG     64
#define SLEN    (LSEQ/SEG)
#define NBH     (BATCH*NH)
#define STATE   (HD*DS)

// ---------------- scratch ----------------
__device__ float g_un [(size_t)ROWS*CCH];       // TF32-rounded LN output
__device__ float g_win[(size_t)CCH*DIN];        // TF32-rounded Win
__device__ float g_wouts[(size_t)DINNER*CCH];   // TF32-rounded Wout*rms_w
__device__ float g_zx [(size_t)ROWS*DIN];
__device__ float g_bc [(size_t)ROWS*32];        // compact conv(B,C) output
__device__ float g_dt [(size_t)ROWS*NH];
__device__ float g_da [(size_t)ROWS*NH];
__device__ float g_y  [(size_t)ROWS*DINNER];
__device__ float g_hend[(size_t)NBH*SEG*STATE];
__device__ float g_hin [(size_t)NBH*SEG*STATE];
__device__ float g_P   [(size_t)NBH*SEG];

// ---------------- helpers ----------------
__device__ __forceinline__ uint32_t f2tf32(float f) {
    uint32_t r;
    asm("cvt.rna.tf32.f32 %0, %1;" : "=r"(r) : "f"(f));
    return r;
}
__device__ __forceinline__ float fsig(float v) {
    return __fdividef(1.f, 1.f + __expf(-v));
}
__device__ __forceinline__ void cp16(float* s, const float* g) {
    uint32_t sa = (uint32_t)__cvta_generic_to_shared(s);
    asm volatile("cp.async.cg.shared.global [%0], [%1], 16;" :: "r"(sa), "l"(g));
}
__device__ __forceinline__ void cp8z(float* s, const float* g, bool p) {
    uint32_t sa = (uint32_t)__cvta_generic_to_shared(s);
    int sz = p ? 8 : 0;
    asm volatile("cp.async.ca.shared.global [%0], [%1], 8, %2;" :: "r"(sa), "l"(g), "r"(sz));
}
#define CP_COMMIT() asm volatile("cp.async.commit_group;")
#define CP_WAIT1()  asm volatile("cp.async.wait_group 1;")
#define CP_WAIT0()  asm volatile("cp.async.wait_group 0;")

#define MMA_TF32(acc, af, bf) \
    asm volatile( \
        "mma.sync.aligned.m16n8k8.row.col.f32.tf32.tf32.f32 " \
        "{%0,%1,%2,%3}, {%4,%5,%6,%7}, {%8,%9}, {%0,%1,%2,%3};" \
        : "+f"(acc[0]), "+f"(acc[1]), "+f"(acc[2]), "+f"(acc[3]) \
        : "r"(af[0]), "r"(af[1]), "r"(af[2]), "r"(af[3]), "r"(bf[0]), "r"(bf[1]))

// ---------------- kernel 0: precompute TF32 weights ----------------
__global__ void prep_kernel(const float* __restrict__ Win,
                            const float* __restrict__ Wout,
                            const float* __restrict__ rms_w)
{
    int i = blockIdx.x * 256 + threadIdx.x;
    if (i < CCH * DIN) g_win[i] = __uint_as_float(f2tf32(Win[i]));
    if (i < DINNER * CCH) {
        int k = i >> 8;
        g_wouts[i] = __uint_as_float(f2tf32(Wout[i] * rms_w[k]));
    }
}

// ---------------- kernel 1: layernorm (writes TF32-rounded un) ----------
__global__ __launch_bounds__(256) void ln_kernel(
    const float* __restrict__ x, const float* __restrict__ gamma,
    const float* __restrict__ beta)
{
    __shared__ float s[256][33];
    __shared__ float s_mu[32], s_rs[32];
    const int b  = blockIdx.y;
    const int l0 = blockIdx.x * 32;
    const int t  = threadIdx.x;

#pragma unroll
    for (int i = 0; i < 32; i++) {
        int flat = i * 256 + t;
        int c  = flat >> 5;
        int lp = flat & 31;
        s[c][lp] = x[((size_t)b * CCH + c) * LSEQ + l0 + lp];
    }
    __syncthreads();

    const int wid = t >> 5, lane = t & 31;
    for (int j = wid; j < 32; j += 8) {
        float v = 0.f, v2 = 0.f;
#pragma unroll
        for (int k = 0; k < 8; k++) {
            float a = s[lane + 32 * k][j];
            v += a; v2 += a * a;
        }
#pragma unroll
        for (int o = 16; o; o >>= 1) {
            v  += __shfl_xor_sync(0xffffffffu, v,  o);
            v2 += __shfl_xor_sync(0xffffffffu, v2, o);
        }
        if (lane == 0) {
            float m = v * (1.f / 256.f);
            s_mu[j] = m;
            s_rs[j] = rsqrtf(v2 * (1.f / 256.f) - m * m + EPS);
        }
    }
    __syncthreads();

#pragma unroll
    for (int i = 0; i < 32; i++) {
        int flat = i * 256 + t;
        int lp = flat >> 8;
        int c  = flat & 255;
        float v = (s[c][lp] - s_mu[lp]) * s_rs[lp] * gamma[c] + beta[c];
        g_un[((size_t)b * LSEQ + l0 + lp) * CCH + c] = __uint_as_float(f2tf32(v));
    }
}

// ---------------- GEMM1: zx = un @ win, TF32, cp.async 2-stage ----------
#define G1_ASTRIDE 36
#define G1_BSTRIDE 136
#define G1_ASZ (128*G1_ASTRIDE)
#define G1_BSZ (32*G1_BSTRIDE)
#define SMEM_G1 ((2*G1_ASZ + 2*G1_BSZ)*4)   // 71680 bytes

__global__ __launch_bounds__(256) void gemm1_kernel(
    const float* __restrict__ dt_bias, const float* __restrict__ A_log)
{
    extern __shared__ float dsm[];
    float* As = dsm;
    float* Bs = dsm + 2*G1_ASZ;
    const int t = threadIdx.x;
    const int warp = t >> 5, lane = t & 31;
    const int wm = warp & 3, wn = warp >> 2;
    const int m0 = blockIdx.y * 128;
    const int n0 = blockIdx.x * 128;
    const int g = lane >> 2, tg = lane & 3;
    const int N = DIN, K = CCH;

    float acc[2][8][4];
#pragma unroll
    for (int mi = 0; mi < 2; mi++)
#pragma unroll
        for (int nj = 0; nj < 8; nj++)
#pragma unroll
            for (int q = 0; q < 4; q++) acc[mi][nj][q] = 0.f;

    auto issue = [&](int tile, int buf) {
        const float* Ag = g_un + (size_t)m0 * K + tile * 32;
        float* Asb = As + buf * G1_ASZ;
#pragma unroll
        for (int i = 0; i < 4; i++) {
            int idx = t + i * 256;
            int row = idx >> 3, kc = (idx & 7) << 2;
            cp16(Asb + row * G1_ASTRIDE + kc, Ag + (size_t)row * K + kc);
        }
        const float* Bg = g_win + (size_t)(tile * 32) * N + n0;
        float* Bsb = Bs + buf * G1_BSZ;
#pragma unroll
        for (int i = 0; i < 8; i++) {
            int idx = t + i * 256;
            int kr = idx >> 6, nc = (idx & 63) << 1;
            cp8z(Bsb + kr * G1_BSTRIDE + nc, Bg + (size_t)kr * N + nc, n0 + nc < N);
        }
    };

    const int T = K / 32;   // 8
    issue(0, 0);
    CP_COMMIT();
    for (int i = 0; i < T; i++) {
        if (i + 1 < T) issue(i + 1, (i + 1) & 1);
        CP_COMMIT();
        CP_WAIT1();
        __syncthreads();
        const float* Asb = As + (i & 1) * G1_ASZ;
        const float* Bsb = Bs + (i & 1) * G1_BSZ;
#pragma unroll
        for (int kk = 0; kk < 32; kk += 8) {
            uint32_t af[2][4];
#pragma unroll
            for (int mi = 0; mi < 2; mi++) {
                int mb = wm * 32 + mi * 16;
                af[mi][0] = __float_as_uint(Asb[(mb + g    ) * G1_ASTRIDE + kk + tg]);
                af[mi][1] = __float_as_uint(Asb[(mb + 8 + g) * G1_ASTRIDE + kk + tg]);
                af[mi][2] = __float_as_uint(Asb[(mb + g    ) * G1_ASTRIDE + kk + 4 + tg]);
                af[mi][3] = __float_as_uint(Asb[(mb + 8 + g) * G1_ASTRIDE + kk + 4 + tg]);
            }
            uint32_t bf[8][2];
#pragma unroll
            for (int nj = 0; nj < 8; nj++) {
                int nb = wn * 64 + nj * 8;
                bf[nj][0] = __float_as_uint(Bsb[(kk + tg    ) * G1_BSTRIDE + nb + g]);
                bf[nj][1] = __float_as_uint(Bsb[(kk + 4 + tg) * G1_BSTRIDE + nb + g]);
            }
#pragma unroll
            for (int mi = 0; mi < 2; mi++)
#pragma unroll
                for (int nj = 0; nj < 8; nj++) MMA_TF32(acc[mi][nj], af[mi], bf[nj]);
        }
        __syncthreads();
    }

#pragma unroll
    for (int mi = 0; mi < 2; mi++) {
        int rbase = m0 + wm * 32 + mi * 16 + g;
#pragma unroll
        for (int nj = 0; nj < 8; nj++) {
            int col = n0 + wn * 64 + nj * 8 + 2 * tg;
            if (col < N) {
                *(float2*)(g_zx + (size_t)rbase * N + col) =
                    make_float2(acc[mi][nj][0], acc[mi][nj][1]);
                *(float2*)(g_zx + (size_t)(rbase + 8) * N + col) =
                    make_float2(acc[mi][nj][2], acc[mi][nj][3]);
            }
        }
    }
    // fused dt/dA: dt cols 1056..1063 -> n-block 8, wn==0, nj==4
    if (blockIdx.x == 8 && wn == 0) {
#pragma unroll
        for (int mi = 0; mi < 2; mi++) {
            int rb_ = m0 + wm * 32 + mi * 16 + g;
#pragma unroll
            for (int q = 0; q < 4; q++) {
                int h = 2 * tg + (q & 1);
                int row = rb_ + ((q >> 1) << 3);
                float v = acc[mi][4][q] + dt_bias[h];
                float d = (v > 20.f) ? v : log1pf(__expf(v));
                float Ah = -__expf(A_log[h]);
                g_dt[(size_t)row * NH + h] = d;
                g_da[(size_t)row * NH + h] = __expf(d * Ah);
            }
        }
    }
}

// ---------------- kernel 4: conv(4)+SiLU, B/C channels -> compact g_bc ----
#define TROW 8
#define NBC  32
__global__ void convbc_kernel(const float* __restrict__ cw,
                              const float* __restrict__ cb)
{
    int id = blockIdx.x * blockDim.x + threadIdx.x;
    if (id >= (ROWS / TROW) * NBC) return;
    int cl = id % NBC;                // 0..31
    int c  = DINNER + cl;             // 512..543
    int rb = id / NBC;
    int r0 = rb * TROW;
    int l0 = r0 & (LSEQ - 1);

    const float* col = g_zx + DINNER + c;
    float w0 = cw[c * 4 + 0], w1 = cw[c * 4 + 1];
    float w2 = cw[c * 4 + 2], w3 = cw[c * 4 + 3];
    float bias = cb[c];

    float vm3 = 0.f, vm2 = 0.f, vm1 = 0.f;
    if (l0 != 0) {
        vm3 = col[(size_t)(r0 - 3) * DIN];
        vm2 = col[(size_t)(r0 - 2) * DIN];
        vm1 = col[(size_t)(r0 - 1) * DIN];
    }
#pragma unroll
    for (int i = 0; i < TROW; i++) {
        float v = col[(size_t)(r0 + i) * DIN];
        float acc = bias + w3 * v + w2 * vm1 + w1 * vm2 + w0 * vm3;
        g_bc[(size_t)(r0 + i) * 32 + cl] = acc * fsig(acc);
        vm3 = vm2; vm2 = vm1; vm1 = v;
    }
}

// ---------------- kernel 5a: segment-local END-STATE only (no y) ---------
__global__ __launch_bounds__(64) void scanA_kernel(
    const float* __restrict__ cw, const float* __restrict__ cb)
{
    const int blk = blockIdx.x;
    const int bh  = blk / SEG;
    const int seg = blk % SEG;
    const int b = bh >> 3, h = bh & 7;
    const int p = threadIdx.x;

    const int c = h * HD + p;
    const float w0 = cw[c * 4 + 0], w1 = cw[c * 4 + 1];
    const float w2 = cw[c * 4 + 2], w3 = cw[c * 4 + 3];
    const float cbias = cb[c];
    const float* colz = g_zx + DINNER + c;

    float hs[DS];
#pragma unroll
    for (int n = 0; n < DS; n++) hs[n] = 0.f;
    float prod = 1.f;

    const size_t r0 = (size_t)b * LSEQ + seg * SLEN;
    float vm3 = 0.f, vm2 = 0.f, vm1 = 0.f;
    if (seg != 0) {
        vm3 = colz[(r0 - 3) * DIN];
        vm2 = colz[(r0 - 2) * DIN];
        vm1 = colz[(r0 - 1) * DIN];
    }

    float dav = g_da[r0 * NH + h];
    float dtv = g_dt[r0 * NH + h];
    float vz  = colz[r0 * DIN];
    const float* bp = g_bc + r0 * 32;
    float4 B0 = *(const float4*)(bp +  0), B1 = *(const float4*)(bp +  4);
    float4 B2 = *(const float4*)(bp +  8), B3 = *(const float4*)(bp + 12);

    for (int l = 0; l < SLEN; l++) {
        const size_t r = r0 + l;
        float dav_n = dav, dtv_n = dtv, vz_n = vz;
        float4 nB0 = B0, nB1 = B1, nB2 = B2, nB3 = B3;
        if (l + 1 < SLEN) {
            const size_t rn = r + 1;
            dav_n = g_da[rn * NH + h];
            dtv_n = g_dt[rn * NH + h];
            vz_n  = colz[rn * DIN];
            const float* bpn = g_bc + rn * 32;
            nB0 = *(const float4*)(bpn +  0); nB1 = *(const float4*)(bpn +  4);
            nB2 = *(const float4*)(bpn +  8); nB3 = *(const float4*)(bpn + 12);
        }

        prod *= dav;
        float ca = cbias + w3 * vz + w2 * vm1 + w1 * vm2 + w0 * vm3;
        float xv = ca * fsig(ca);
        vm3 = vm2; vm2 = vm1; vm1 = vz;

        float bb[DS] = {B0.x,B0.y,B0.z,B0.w, B1.x,B1.y,B1.z,B1.w,
                        B2.x,B2.y,B2.z,B2.w, B3.x,B3.y,B3.z,B3.w};

        float t1 = dtv * xv;
#pragma unroll
        for (int n = 0; n < DS; n++)
            hs[n] = fmaf(dav, hs[n], t1 * bb[n]);

        dav = dav_n; dtv = dtv_n; vz = vz_n;
        B0 = nB0; B1 = nB1; B2 = nB2; B3 = nB3;
    }

    float* he = g_hend + ((size_t)bh * SEG + seg) * STATE + p * DS;
#pragma unroll
    for (int n = 0; n < DS; n += 4)
        *(float4*)(he + n) = make_float4(hs[n], hs[n+1], hs[n+2], hs[n+3]);
    if (p == 0) g_P[(size_t)bh * SEG + seg] = prod;
}

// ---------------- kernel 5b: compose segment states (128 blocks) ---------
__global__ __launch_bounds__(512) void scanB_kernel()
{
    const int blk = blockIdx.x;
    const int bh = blk >> 1;
    const int pn = (blk & 1) * 512 + threadIdx.x;
    __shared__ float sP[SEG];
    if (threadIdx.x < SEG) sP[threadIdx.x] = g_P[(size_t)bh * SEG + threadIdx.x];
    __syncthreads();

    float h = 0.f;
    const size_t base = (size_t)bh * SEG * STATE + pn;
    for (int seg = 0; seg < SEG; seg++) {
        g_hin[base + (size_t)seg * STATE] = h;
        h = fmaf(sP[seg], h, g_hend[base + (size_t)seg * STATE]);
    }
}

// ---------------- kernel 5c: full scan from hin, writes y ONCE -----------
__global__ __launch_bounds__(64) void scanC_kernel(
    const float* __restrict__ Dp, const float* __restrict__ cw,
    const float* __restrict__ cb)
{
    const int blk = blockIdx.x;
    const int bh  = blk / SEG;
    const int seg = blk % SEG;
    const int b = bh >> 3, h = bh & 7;
    const int p = threadIdx.x;
    const float Dh = Dp[h];

    const int c = h * HD + p;
    const float w0 = cw[c * 4 + 0], w1 = cw[c * 4 + 1];
    const float w2 = cw[c * 4 + 2], w3 = cw[c * 4 + 3];
    const float cbias = cb[c];
    const float* colz = g_zx + DINNER + c;

    // initial state from hin
    float hs[DS];
    const float* hp = g_hin + ((size_t)bh * SEG + seg) * STATE + p * DS;
#pragma unroll
    for (int n = 0; n < DS; n += 4) {
        float4 v = *(const float4*)(hp + n);
        hs[n] = v.x; hs[n+1] = v.y; hs[n+2] = v.z; hs[n+3] = v.w;
    }

    const size_t r0 = (size_t)b * LSEQ + seg * SLEN;
    float vm3 = 0.f, vm2 = 0.f, vm1 = 0.f;
    if (seg != 0) {
        vm3 = colz[(r0 - 3) * DIN];
        vm2 = colz[(r0 - 2) * DIN];
        vm1 = colz[(r0 - 1) * DIN];
    }

    float dav = g_da[r0 * NH + h];
    float dtv = g_dt[r0 * NH + h];
    float vz  = colz[r0 * DIN];
    const float* bp = g_bc + r0 * 32;
    float4 B0 = *(const float4*)(bp +  0), B1 = *(const float4*)(bp +  4);
    float4 B2 = *(const float4*)(bp +  8), B3 = *(const float4*)(bp + 12);
    float4 C0 = *(const float4*)(bp + 16), C1 = *(const float4*)(bp + 20);
    float4 C2 = *(const float4*)(bp + 24), C3 = *(const float4*)(bp + 28);

    for (int l = 0; l < SLEN; l++) {
        const size_t r = r0 + l;
        float dav_n = dav, dtv_n = dtv, vz_n = vz;
        float4 nB0 = B0, nB1 = B1, nB2 = B2, nB3 = B3;
        float4 nC0 = C0, nC1 = C1, nC2 = C2, nC3 = C3;
        if (l + 1 < SLEN) {
            const size_t rn = r + 1;
            dav_n = g_da[rn * NH + h];
            dtv_n = g_dt[rn * NH + h];
            vz_n  = colz[rn * DIN];
            const float* bpn = g_bc + rn * 32;
            nB0 = *(const float4*)(bpn +  0); nB1 = *(const float4*)(bpn +  4);
            nB2 = *(const float4*)(bpn +  8); nB3 = *(const float4*)(bpn + 12);
            nC0 = *(const float4*)(bpn + 16); nC1 = *(const float4*)(bpn + 20);
            nC2 = *(const float4*)(bpn + 24); nC3 = *(const float4*)(bpn + 28);
        }

        float ca = cbias + w3 * vz + w2 * vm1 + w1 * vm2 + w0 * vm3;
        float xv = ca * fsig(ca);
        vm3 = vm2; vm2 = vm1; vm1 = vz;

        float bb[DS] = {B0.x,B0.y,B0.z,B0.w, B1.x,B1.y,B1.z,B1.w,
                        B2.x,B2.y,B2.z,B2.w, B3.x,B3.y,B3.z,B3.w};
        float cc[DS] = {C0.x,C0.y,C0.z,C0.w, C1.x,C1.y,C1.z,C1.w,
                        C2.x,C2.y,C2.z,C2.w, C3.x,C3.y,C3.z,C3.w};

        float t1 = dtv * xv;
        float yv0 = 0.f, yv1 = 0.f;
#pragma unroll
        for (int n = 0; n < DS; n += 2) {
            hs[n]   = fmaf(dav, hs[n],   t1 * bb[n]);
            hs[n+1] = fmaf(dav, hs[n+1], t1 * bb[n+1]);
            yv0 = fmaf(hs[n],   cc[n],   yv0);
            yv1 = fmaf(hs[n+1], cc[n+1], yv1);
        }
        g_y[r * DINNER + h * HD + p] = yv0 + yv1 + Dh * xv;

        dav = dav_n; dtv = dtv_n; vz = vz_n;
        B0 = nB0; B1 = nB1; B2 = nB2; B3 = nB3;
        C0 = nC0; C1 = nC1; C2 = nC2; C3 = nC3;
    }
}

// ---------------- GEMM2 fused, pipelined: gate + RMSNorm +
// out_proj + transpose + residual.
#define G2_ASTRIDE 36
#define G2_BSTRIDE 264
#define G2_BSZ (32*G2_BSTRIDE)
#define G2_POOLF (64*G2_ASTRIDE + 2*G2_BSZ)    // 19200 floats
#define SMEM_G2 (G2_POOLF*4)                   // 76800 bytes

__global__ __launch_bounds__(256) void gemm2_fused_kernel(
    const float* __restrict__ x, float* __restrict__ out)
{
    extern __shared__ float pool[];
    float* As = pool;                   // [64][36]
    float* Bs = pool + 64 * G2_ASTRIDE; // [2][32][264]
    const int t = threadIdx.x;
    const int warp = t >> 5, lane = t & 31;
    const int wm = warp & 1, wn = warp >> 1;
    const int m0 = blockIdx.x * 64;
    const int g = lane >> 2, tg = lane & 3;
    const int r0 = t >> 3, kc0 = (t & 7) << 2;

    float acc[2][8][4];
#pragma unroll
    for (int mi = 0; mi < 2; mi++)
#pragma unroll
        for (int nj = 0; nj < 8; nj++)
#pragma unroll
            for (int q = 0; q < 4; q++) acc[mi][nj][q] = 0.f;
    float sq0 = 0.f, sq1 = 0.f;

    auto issueB = [&](int k0, int buf) {
        float* Bsb = Bs + buf * G2_BSZ;
        const float* Wg = g_wouts + (size_t)k0 * CCH;
#pragma unroll
        for (int i = 0; i < 8; i++) {
            int idx = t + i * 256;
            int kr = idx >> 6, nc = (idx & 63) << 2;
            cp16(Bsb + kr * G2_BSTRIDE + nc, Wg + (size_t)kr * CCH + nc);
        }
    };

    issueB(0, 0);
    CP_COMMIT();
    float4 ry0, ry1, rz0, rz1;
    {
        size_t rra = (size_t)(m0 + r0);
        size_t rrb = (size_t)(m0 + r0 + 32);
        ry0 = *(const float4*)(g_y  + rra * DINNER + kc0);
        rz0 = *(const float4*)(g_zx + rra * DIN    + kc0);
        ry1 = *(const float4*)(g_y  + rrb * DINNER + kc0);
        rz1 = *(const float4*)(g_zx + rrb * DIN    + kc0);
    }

    const int NT = DINNER / 32;   // 16
    for (int kt = 0; kt < NT; kt++) {
        {
            float v0 = ry0.x * (rz0.x * fsig(rz0.x));
            float v1 = ry0.y * (rz0.y * fsig(rz0.y));
            float v2 = ry0.z * (rz0.z * fsig(rz0.z));
            float v3 = ry0.w * (rz0.w * fsig(rz0.w));
            As[r0 * G2_ASTRIDE + kc0 + 0] = __uint_as_float(f2tf32(v0));
            As[r0 * G2_ASTRIDE + kc0 + 1] = __uint_as_float(f2tf32(v1));
            As[r0 * G2_ASTRIDE + kc0 + 2] = __uint_as_float(f2tf32(v2));
            As[r0 * G2_ASTRIDE + kc0 + 3] = __uint_as_float(f2tf32(v3));
            sq0 += v0*v0 + v1*v1 + v2*v2 + v3*v3;
            float u0 = ry1.x * (rz1.x * fsig(rz1.x));
            float u1 = ry1.y * (rz1.y * fsig(rz1.y));
            float u2 = ry1.z * (rz1.z * fsig(rz1.z));
            float u3 = ry1.w * (rz1.w * fsig(rz1.w));
            As[(r0 + 32) * G2_ASTRIDE + kc0 + 0] = __uint_as_float(f2tf32(u0));
            As[(r0 + 32) * G2_ASTRIDE + kc0 + 1] = __uint_as_float(f2tf32(u1));
            As[(r0 + 32) * G2_ASTRIDE + kc0 + 2] = __uint_as_float(f2tf32(u2));
            As[(r0 + 32) * G2_ASTRIDE + kc0 + 3] = __uint_as_float(f2tf32(u3));
            sq1 += u0*u0 + u1*u1 + u2*u2 + u3*u3;
        }
        if (kt + 1 < NT) {
            issueB((kt + 1) * 32, (kt + 1) & 1);
            CP_COMMIT();
            int k1 = (kt + 1) * 32 + kc0;
            size_t rra = (size_t)(m0 + r0);
            size_t rrb = (size_t)(m0 + r0 + 32);
            ry0 = *(const float4*)(g_y  + rra * DINNER + k1);
            rz0 = *(const float4*)(g_zx + rra * DIN    + k1);
            ry1 = *(const float4*)(g_y  + rrb * DINNER + k1);
            rz1 = *(const float4*)(g_zx + rrb * DIN    + k1);
            CP_WAIT1();
        } else {
            CP_WAIT0();
        }
        __syncthreads();

        const float* Bsb = Bs + (kt & 1) * G2_BSZ;
#pragma unroll
        for (int kk = 0; kk < 32; kk += 8) {
            uint32_t af[2][4];
#pragma unroll
            for (int mi = 0; mi < 2; mi++) {
                int mb = wm * 32 + mi * 16;
                af[mi][0] = __float_as_uint(As[(mb + g    ) * G2_ASTRIDE + kk + tg]);
                af[mi][1] = __float_as_uint(As[(mb + 8 + g) * G2_ASTRIDE + kk + tg]);
                af[mi][2] = __float_as_uint(As[(mb + g    ) * G2_ASTRIDE + kk + 4 + tg]);
                af[mi][3] = __float_as_uint(As[(mb + 8 + g) * G2_ASTRIDE + kk + 4 + tg]);
            }
            uint32_t bf[8][2];
#pragma unroll
            for (int nj = 0; nj < 8; nj++) {
                int nb = wn * 64 + nj * 8;
                bf[nj][0] = __float_as_uint(Bsb[(kk + tg    ) * G2_BSTRIDE + nb + g]);
                bf[nj][1] = __float_as_uint(Bsb[(kk + 4 + tg) * G2_BSTRIDE + nb + g]);
            }
#pragma unroll
            for (int mi = 0; mi < 2; mi++)
#pragma unroll
                for (int nj = 0; nj < 8; nj++) MMA_TF32(acc[mi][nj], af[mi], bf[nj]);
        }
        __syncthreads();
    }

    // rn reduction
    float* sq = pool;
    sq[r0 * 8 + (t & 7)] = sq0;
    sq[(r0 + 32) * 8 + (t & 7)] = sq1;
    __syncthreads();
    float* rn = pool + 512;
    if (t < 64) {
        float s = 0.f;
#pragma unroll
        for (int j = 0; j < 8; j++) s += sq[t * 8 + j];
        rn[t] = rsqrtf(s * (1.f / (float)DINNER) + EPS);
    }
    __syncthreads();
    float rsc[2][2];
#pragma unroll
    for (int mi = 0; mi < 2; mi++) {
        rsc[mi][0] = rn[wm * 32 + mi * 16 + g];
        rsc[mi][1] = rn[wm * 32 + mi * 16 + 8 + g];
    }
    __syncthreads();

    // epilogue: transpose + residual
    float* epi = pool;
    const int b  = m0 >> 12;
    const int l0 = m0 & (LSEQ - 1);
#pragma unroll
    for (int cj = 0; cj < 4; cj++) {
        if (wn == cj) {
#pragma unroll
            for (int mi = 0; mi < 2; mi++)
#pragma unroll
                for (int nj = 0; nj < 8; nj++)
#pragma unroll
                    for (int q = 0; q < 4; q++) {
                        int Rl = wm * 32 + mi * 16 + g + ((q >> 1) << 3);
                        int cl = nj * 8 + 2 * tg + (q & 1);
                        epi[cl * 68 + Rl] = acc[mi][nj][q] * rsc[mi][q >> 1];
                    }
        }
        __syncthreads();
        {
            int c = t >> 2, sg2 = t & 3;
            size_t ob = ((size_t)b * CCH + cj * 64 + c) * LSEQ + l0 + sg2 * 16;
#pragma unroll
            for (int j = 0; j < 4; j++) {
                float4 e  = *(float4*)(epi + c * 68 + sg2 * 16 + j * 4);
                float4 xr = *(const float4*)(x + ob + j * 4);
                e.x += xr.x; e.y += xr.y; e.z += xr.z; e.w += xr.w;
                *(float4*)(out + ob + j * 4) = e;
            }
        }
        __syncthreads();
    }
}

extern "C" void kernel_launch(void* const* d_in, const int* in_sizes, int n_in,
                              void* d_out, int out_size)
{
    const float* x       = (const float*)d_in[0];
    const float* ln_g    = (const float*)d_in[1];
    const float* ln_b    = (const float*)d_in[2];
    const float* Win     = (const float*)d_in[3];
    const float* Wout    = (const float*)d_in[4];
    const float* conv_w  = (const float*)d_in[5];
    const float* conv_b  = (const float*)d_in[6];
    const float* dt_bias = (const float*)d_in[7];
    const float* A_log   = (const float*)d_in[8];
    const float* Dp      = (const float*)d_in[9];
    const float* rms_w   = (const float*)d_in[10];
    float* out = (float*)d_out;

    cudaFuncSetAttribute(gemm1_kernel,
                         cudaFuncAttributeMaxDynamicSharedMemorySize, SMEM_G1);
    cudaFuncSetAttribute(gemm2_fused_kernel,
                         cudaFuncAttributeMaxDynamicSharedMemorySize, SMEM_G2);

    // 0) precompute TF32 weights
    prep_kernel<<<(CCH * DIN + 255) / 256, 256>>>(Win, Wout, rms_w);

    // 1) layernorm (writes pre-rounded un)
    ln_kernel<<<dim3(LSEQ / 32, BATCH), 256>>>(x, ln_g, ln_b);

    // 2) in_proj GEMM with dt/dA epilogue
    gemm1_kernel<<<dim3((DIN + 127) / 128, ROWS / 128), 256, SMEM_G1>>>(
        dt_bias, A_log);

    // 3) conv + silu, B/C channels -> compact g_bc
    convbc_kernel<<<((ROWS / TROW) * NBC + 255) / 256, 256>>>(conv_w, conv_b);

    // 4) segmented SSM scan: end-states -> compose -> full scan (y once)
    scanA_kernel<<<NBH * SEG, HD>>>(conv_w, conv_b);
    scanB_kernel<<<NBH * 2, 512>>>();
    scanC_kernel<<<NBH * SEG, HD>>>(Dp, conv_w, conv_b);

    // 5) fused pipelined: gate + rmsnorm + out_proj + transpose + residual
    gemm2_fused_kernel<<<ROWS / 64, 256, SMEM_G2>>>(x, out);
}